// round 10
// baseline (speedup 1.0000x reference)
#include <cuda_runtime.h>
#include <cuda_fp16.h>
#include <cstdint>

// MoE dense 8-expert: D_IN=6, H=32, D_OUT=2, B=1M, fp32.
// R10 = R7 structure with fp16 cross-packed splits:
//  - layer-2: 4 k16 MMAs per (nf,mf) instead of 6. Each MMA computes
//    (a_hi+a_lo)*b_hi exactly via A=[ahi|alo] k-packing + duplicated-B
//    (b1=b0). Only dropped term: a*W2_lo (~2^-11 rel, under 1e-3 budget).
//  - layer-1: 1 cross-packed k16 (exact x*W1_hi) + 1 k8 (xhi*W1_lo).
//  - b1 folded at k=6 slot; b2 via C-operand; gate scalar FFMA2 + SHFL.
// Grid = 2 CTAs/SM.

#define ED 8
#define DI 6
#define HH 32
#define DO 2

typedef unsigned long long u64;
typedef unsigned int u32;

// ---- scalar helpers ----
__device__ __forceinline__ void ffma2_acc(u64& acc, u64 a, u64 b) {
    asm("fma.rn.f32x2 %0, %1, %2, %0;" : "+l"(acc) : "l"(a), "l"(b));
}
__device__ __forceinline__ u64 pack_dup(float v) {
    u64 r; asm("mov.b64 %0, {%1, %1};" : "=l"(r) : "r"(__float_as_uint(v))); return r;
}
__device__ __forceinline__ float2 unpack2(u64 v) {
    float2 f; asm("mov.b64 {%0, %1}, %2;" : "=f"(f.x), "=f"(f.y) : "l"(v)); return f;
}
// pack two f32 -> f16x2 (element0 = lo_e arg, element1 = hi_e arg)
__device__ __forceinline__ u32 f16x2_of(float lo_e, float hi_e) {
    u32 r; asm("cvt.rn.f16x2.f32 %0, %1, %2;" : "=r"(r) : "f"(hi_e), "f"(lo_e)); return r;
}
__device__ __forceinline__ float f16lo(u32 p) {
    float f; asm("{.reg .b16 l,h; mov.b32 {l,h}, %1; cvt.f32.f16 %0, l;}" : "=f"(f) : "r"(p)); return f;
}
__device__ __forceinline__ float f16hi(u32 p) {
    float f; asm("{.reg .b16 l,h; mov.b32 {l,h}, %1; cvt.f32.f16 %0, h;}" : "=f"(f) : "r"(p)); return f;
}

// ---- MMA helpers (fp16 in, fp32 accum) ----
__device__ __forceinline__ void mma_f16(float& d0, float& d1, float& d2, float& d3,
                                        u32 a0, u32 a1, u32 a2, u32 a3,
                                        u32 b0, u32 b1) {
    asm("mma.sync.aligned.m16n8k16.row.col.f32.f16.f16.f32 "
        "{%0,%1,%2,%3}, {%4,%5,%6,%7}, {%8,%9}, {%0,%1,%2,%3};"
        : "+f"(d0), "+f"(d1), "+f"(d2), "+f"(d3)
        : "r"(a0), "r"(a1), "r"(a2), "r"(a3), "r"(b0), "r"(b1));
}
__device__ __forceinline__ void mma_f16_c(float& d0, float& d1, float& d2, float& d3,
                                          u32 a0, u32 a1, u32 a2, u32 a3,
                                          u32 b0, u32 b1,
                                          float c0, float c1, float c2, float c3) {
    asm("mma.sync.aligned.m16n8k16.row.col.f32.f16.f16.f32 "
        "{%0,%1,%2,%3}, {%4,%5,%6,%7}, {%8,%9}, {%10,%11,%12,%13};"
        : "=f"(d0), "=f"(d1), "=f"(d2), "=f"(d3)
        : "r"(a0), "r"(a1), "r"(a2), "r"(a3), "r"(b0), "r"(b1),
          "f"(c0), "f"(c1), "f"(c2), "f"(c3));
}
__device__ __forceinline__ void mma_f16_k8(float& d0, float& d1, float& d2, float& d3,
                                           u32 a0, u32 a1, u32 b0) {
    asm("mma.sync.aligned.m16n8k8.row.col.f32.f16.f16.f32 "
        "{%0,%1,%2,%3}, {%4,%5}, {%6}, {%0,%1,%2,%3};"
        : "+f"(d0), "+f"(d1), "+f"(d2), "+f"(d3)
        : "r"(a0), "r"(a1), "r"(b0));
}

__global__ __launch_bounds__(128)
void moe_mma_kernel(const float* __restrict__ gx,
                    const float* __restrict__ gW1, const float* __restrict__ gb1,
                    const float* __restrict__ gW2, const float* __restrict__ gb2,
                    const float* __restrict__ gW3, const float* __restrict__ gb3,
                    const float* __restrict__ gWg1, const float* __restrict__ gbg1,
                    const float* __restrict__ gWg2, const float* __restrict__ gbg2,
                    float* __restrict__ gout, int B, int NT)
{
    __shared__ __align__(16) float sx[4 * 192];               // per-warp x tiles
    __shared__ __align__(16) char  sBfrag[ED * 4 * 32 * 16];  // layer-2 W2_hi frags [e][chunk][lane]
    __shared__ __align__(16) char  sB1frag[ED * 2 * 32 * 16]; // layer-1 W1 hi|lo frags, b1 @k=6
    __shared__ __align__(16) float sb2[ED * HH];
    __shared__ __align__(16) float sW3[ED * HH * DO];
    __shared__ __align__(16) float sb3[ED * DO];
    __shared__ __align__(16) float sWg1[DI * HH];
    __shared__ __align__(16) float sbg1[HH];
    __shared__ __align__(16) float sWg2[HH * ED];
    __shared__ __align__(16) float sbg2[ED];

    const int tid  = threadIdx.x;
    const int w    = tid >> 5;
    const int lane = tid & 31;
    const int g    = lane >> 2;   // groupID
    const int q    = lane & 3;    // threadID in group

    // ---- stage small weights ----
    for (int i = tid; i < ED * HH;      i += 128) sb2[i]  = gb2[i];
    for (int i = tid; i < ED * HH * DO; i += 128) sW3[i]  = gW3[i];
    for (int i = tid; i < ED * DO;      i += 128) sb3[i]  = gb3[i];
    for (int i = tid; i < DI * HH;      i += 128) sWg1[i] = gWg1[i];
    for (int i = tid; i < HH;           i += 128) sbg1[i] = gbg1[i];
    for (int i = tid; i < HH * ED;      i += 128) sWg2[i] = gWg2[i];
    for (int i = tid; i < ED;           i += 128) sbg2[i] = gbg2[i];

    // ---- precompute per-lane B fragments ----
    for (int e = w * 2; e < w * 2 + 2; e++) {
        // layer-2: W2_hi only, per k8-chunk c; lane holds pair (k=8c+2q, 8c+2q+1) for n=8nf+g
        #pragma unroll
        for (int c = 0; c < 4; c++) {
            u32 hi4[4];
            #pragma unroll
            for (int nf = 0; nf < 4; nf++) {
                const int n  = nf * 8 + g;
                const int k0 = c * 8 + 2 * q;
                hi4[nf] = f16x2_of(gW2[e * 1024 + k0 * 32 + n],
                                   gW2[e * 1024 + (k0 + 1) * 32 + n]);
            }
            *(uint4*)(sBfrag + ((e * 4 + c) * 32 + lane) * 16) = make_uint4(hi4[0], hi4[1], hi4[2], hi4[3]);
        }
        // layer-1: W1 hi + lo (k8 frags; q==3 carries b1 at k=6, 0 at k=7)
        {
            u32 hi4[4], lo4[4];
            #pragma unroll
            for (int nf = 0; nf < 4; nf++) {
                const int n = nf * 8 + g;
                float w0, w1;
                if (q < 3) {
                    w0 = gW1[e * 192 + (2 * q    ) * 32 + n];
                    w1 = gW1[e * 192 + (2 * q + 1) * 32 + n];
                } else {
                    w0 = gb1[e * 32 + n];
                    w1 = 0.0f;
                }
                const u32 h = f16x2_of(w0, w1);
                hi4[nf] = h;
                lo4[nf] = f16x2_of(w0 - f16lo(h), w1 - f16hi(h));
            }
            *(uint4*)(sB1frag + ((e * 2 + 0) * 32 + lane) * 16) = make_uint4(hi4[0], hi4[1], hi4[2], hi4[3]);
            *(uint4*)(sB1frag + ((e * 2 + 1) * 32 + lane) * 16) = make_uint4(lo4[0], lo4[1], lo4[2], lo4[3]);
        }
    }
    __syncthreads();

    const int lim6 = B * DI;
    const float fz = 0.0f;

    // ---- persistent per-warp tile loop (32 tokens per warp) ----
    for (int tile = blockIdx.x; tile < NT; tile += gridDim.x) {
        const int base = tile * 128 + w * 32;
        float* sxw = sx + w * 192;
        #pragma unroll
        for (int i = 0; i < 6; i++) {
            const int idx = base * DI + i * 32 + lane;
            sxw[i * 32 + lane] = (idx < lim6) ? gx[idx] : 0.0f;
        }
        __syncwarp();

        // ---- x A-fragments (fp16 hi + exact residual lo); q==3 -> 1.0 bias slot ----
        u32 xhi[2][2], xlo[2][2];
        #pragma unroll
        for (int mf = 0; mf < 2; mf++) {
            const int r0 = 16 * mf + g, r1 = r0 + 8;
            float v00, v01, v10, v11;
            if (q < 3) {
                v00 = sxw[r0 * DI + 2 * q]; v01 = sxw[r0 * DI + 2 * q + 1];
                v10 = sxw[r1 * DI + 2 * q]; v11 = sxw[r1 * DI + 2 * q + 1];
            } else {
                v00 = 1.0f; v01 = 0.0f; v10 = 1.0f; v11 = 0.0f;
            }
            const u32 h0 = f16x2_of(v00, v01);
            const u32 h1 = f16x2_of(v10, v11);
            xhi[mf][0] = h0; xhi[mf][1] = h1;
            xlo[mf][0] = f16x2_of(v00 - f16lo(h0), v01 - f16hi(h0));
            xlo[mf][1] = f16x2_of(v10 - f16lo(h1), v11 - f16hi(h1));
        }

        // ---- gate for token (g + 8q): packed FFMA2 ----
        float gg[ED];
        {
            const float* xg = sxw + (g + 8 * q) * DI;
            u64 gacc[HH / 2];
            const u64* bg1p = (const u64*)sbg1;
            #pragma unroll
            for (int i = 0; i < HH / 2; i++) gacc[i] = bg1p[i];
            #pragma unroll
            for (int d = 0; d < DI; d++) {
                const u64 xd = pack_dup(xg[d]);
                const u64* wr = (const u64*)(sWg1 + d * HH);
                #pragma unroll
                for (int i = 0; i < HH / 2; i++) ffma2_acc(gacc[i], xd, wr[i]);
            }
            u64 lacc[ED / 2];
            const u64* bg2p = (const u64*)sbg2;
            #pragma unroll
            for (int i = 0; i < ED / 2; i++) lacc[i] = bg2p[i];
            #pragma unroll
            for (int i = 0; i < HH / 2; i++) {
                const float2 t = unpack2(gacc[i]);
                const u64 hj0 = pack_dup(fmaxf(t.x, 0.0f));
                const u64 hj1 = pack_dup(fmaxf(t.y, 0.0f));
                const u64* wr0 = (const u64*)(sWg2 + (2 * i    ) * ED);
                const u64* wr1 = (const u64*)(sWg2 + (2 * i + 1) * ED);
                #pragma unroll
                for (int k2 = 0; k2 < ED / 2; k2++) {
                    ffma2_acc(lacc[k2], hj0, wr0[k2]);
                    ffma2_acc(lacc[k2], hj1, wr1[k2]);
                }
            }
            float lg[ED];
            #pragma unroll
            for (int i = 0; i < ED / 2; i++) {
                const float2 t = unpack2(lacc[i]);
                lg[2 * i] = t.x; lg[2 * i + 1] = t.y;
            }
            float mx = lg[0];
            #pragma unroll
            for (int e = 1; e < ED; e++) mx = fmaxf(mx, lg[e]);
            float s = 0.0f;
            #pragma unroll
            for (int e = 0; e < ED; e++) { lg[e] = __expf(lg[e] - mx); s += lg[e]; }
            const float inv = 1.0f / s;
            #pragma unroll
            for (int e = 0; e < ED; e++) gg[e] = lg[e] * inv;
        }

        float2 oP[4];
        #pragma unroll
        for (int m = 0; m < 4; m++) oP[m] = make_float2(0.0f, 0.0f);

        // ---- experts ----
        #pragma unroll
        for (int e = 0; e < ED; e++) {
            const uint4 bh4 = *(const uint4*)(sB1frag + ((e * 2 + 0) * 32 + lane) * 16);
            const uint4 bl4 = *(const uint4*)(sB1frag + ((e * 2 + 1) * 32 + lane) * 16);
            uint4 cB[4];
            #pragma unroll
            for (int c = 0; c < 4; c++)
                cB[c] = *(const uint4*)(sBfrag + ((e * 4 + c) * 32 + lane) * 16);

            // layer 1: per nf, 1 cross-packed k16 (exact x*W1_hi, C=0) + 1 k8 (xhi*W1_lo)
            float h1d[2][4][4];
            #pragma unroll
            for (int nf = 0; nf < 4; nf++) {
                const u32 bh = (nf == 0) ? bh4.x : (nf == 1) ? bh4.y : (nf == 2) ? bh4.z : bh4.w;
                const u32 bl = (nf == 0) ? bl4.x : (nf == 1) ? bl4.y : (nf == 2) ? bl4.z : bl4.w;
                #pragma unroll
                for (int mf = 0; mf < 2; mf++) {
                    mma_f16_c(h1d[mf][nf][0], h1d[mf][nf][1], h1d[mf][nf][2], h1d[mf][nf][3],
                              xhi[mf][0], xhi[mf][1], xlo[mf][0], xlo[mf][1],
                              bh, bh, fz, fz, fz, fz);
                    mma_f16_k8(h1d[mf][nf][0], h1d[mf][nf][1], h1d[mf][nf][2], h1d[mf][nf][3],
                               xhi[mf][0], xhi[mf][1], bl);
                }
            }

            // relu + exact fp16 split: D n-frag c -> layer-2 A chunk c (no reshuffle)
            u32 ahi[2][4][2], alo[2][4][2];
            #pragma unroll
            for (int mf = 0; mf < 2; mf++) {
                #pragma unroll
                for (int c = 0; c < 4; c++) {
                    const float f0 = fmaxf(h1d[mf][c][0], 0.0f);
                    const float f1 = fmaxf(h1d[mf][c][1], 0.0f);
                    const float f2 = fmaxf(h1d[mf][c][2], 0.0f);
                    const float f3 = fmaxf(h1d[mf][c][3], 0.0f);
                    const u32 hA = f16x2_of(f0, f1);   // row g
                    const u32 hB = f16x2_of(f2, f3);   // row g+8
                    ahi[mf][c][0] = hA;
                    ahi[mf][c][1] = hB;
                    alo[mf][c][0] = f16x2_of(f0 - f16lo(hA), f1 - f16hi(hA));
                    alo[mf][c][1] = f16x2_of(f2 - f16lo(hB), f3 - f16hi(hB));
                }
            }

            // b2 / W3 fragments
            float2 b2p[4]; float4 w34[4];
            #pragma unroll
            for (int nf = 0; nf < 4; nf++) {
                b2p[nf] = *(const float2*)&sb2[e * HH + nf * 8 + 2 * q];
                w34[nf] = *(const float4*)&sW3[(e * HH + nf * 8 + 2 * q) * DO];
            }

            // layer-2: per (nf,mf), 4 cross-packed k16 MMAs: sum_c (a_hi+a_lo)*W2_hi
            float dd[2][4][4];
            #pragma unroll
            for (int nf = 0; nf < 4; nf++) {
                const u32 b0 = (nf == 0) ? cB[0].x : (nf == 1) ? cB[0].y : (nf == 2) ? cB[0].z : cB[0].w;
                const u32 b1 = (nf == 0) ? cB[1].x : (nf == 1) ? cB[1].y : (nf == 2) ? cB[1].z : cB[1].w;
                const u32 b2c = (nf == 0) ? cB[2].x : (nf == 1) ? cB[2].y : (nf == 2) ? cB[2].z : cB[2].w;
                const u32 b3c = (nf == 0) ? cB[3].x : (nf == 1) ? cB[3].y : (nf == 2) ? cB[3].z : cB[3].w;
                #pragma unroll
                for (int mf = 0; mf < 2; mf++) {
                    mma_f16_c(dd[mf][nf][0], dd[mf][nf][1], dd[mf][nf][2], dd[mf][nf][3],
                              ahi[mf][0][0], ahi[mf][0][1], alo[mf][0][0], alo[mf][0][1],
                              b0, b0,
                              b2p[nf].x, b2p[nf].y, b2p[nf].x, b2p[nf].y);
                    mma_f16(dd[mf][nf][0], dd[mf][nf][1], dd[mf][nf][2], dd[mf][nf][3],
                            ahi[mf][1][0], ahi[mf][1][1], alo[mf][1][0], alo[mf][1][1],
                            b1, b1);
                    mma_f16(dd[mf][nf][0], dd[mf][nf][1], dd[mf][nf][2], dd[mf][nf][3],
                            ahi[mf][2][0], ahi[mf][2][1], alo[mf][2][0], alo[mf][2][1],
                            b2c, b2c);
                    mma_f16(dd[mf][nf][0], dd[mf][nf][1], dd[mf][nf][2], dd[mf][nf][3],
                            ahi[mf][3][0], ahi[mf][3][1], alo[mf][3][0], alo[mf][3][1],
                            b3c, b3c);
                }
            }

            // epilogue: relu + layer3 + gate-weighted accumulate (b2 already in D)
            const float y0b = sb3[e * DO + 0];
            const float y1b = sb3[e * DO + 1];
            #pragma unroll
            for (int m = 0; m < 4; m++) {
                const int mf = m >> 1, r = m & 1;
                float y0 = y0b, y1 = y1b;
                #pragma unroll
                for (int nf = 0; nf < 4; nf++) {
                    const float ha = fmaxf(dd[mf][nf][r * 2 + 0], 0.0f);
                    const float hb = fmaxf(dd[mf][nf][r * 2 + 1], 0.0f);
                    y0 = fmaf(ha, w34[nf].x, y0);
                    y1 = fmaf(ha, w34[nf].y, y1);
                    y0 = fmaf(hb, w34[nf].z, y0);
                    y1 = fmaf(hb, w34[nf].w, y1);
                }
                const float ge = __shfl_sync(0xffffffffu, gg[e], (lane & 28) + m);
                oP[m].x = fmaf(ge, y0, oP[m].x);
                oP[m].y = fmaf(ge, y1, oP[m].y);
            }
        }

        // ---- quad butterfly reduction, write own token ----
        #pragma unroll
        for (int m = 0; m < 4; m++) {
            #pragma unroll
            for (int o = 1; o <= 2; o <<= 1) {
                oP[m].x += __shfl_xor_sync(0xffffffffu, oP[m].x, o);
                oP[m].y += __shfl_xor_sync(0xffffffffu, oP[m].y, o);
            }
        }
        float2 res = oP[0];
        if (q == 1) res = oP[1];
        if (q == 2) res = oP[2];
        if (q == 3) res = oP[3];
        const int t = base + g + 8 * q;
        if (t < B) ((float2*)gout)[t] = res;
    }
}

extern "C" void kernel_launch(void* const* d_in, const int* in_sizes, int n_in,
                              void* d_out, int out_size)
{
    const float* x   = (const float*)d_in[0];
    const float* W1  = (const float*)d_in[1];
    const float* b1  = (const float*)d_in[2];
    const float* W2  = (const float*)d_in[3];
    const float* b2  = (const float*)d_in[4];
    const float* W3  = (const float*)d_in[5];
    const float* b3  = (const float*)d_in[6];
    const float* Wg1 = (const float*)d_in[7];
    const float* bg1 = (const float*)d_in[8];
    const float* Wg2 = (const float*)d_in[9];
    const float* bg2 = (const float*)d_in[10];
    float* out = (float*)d_out;

    const int B  = in_sizes[0] / DI;
    const int NT = (B + 127) / 128;

    int nsm = 148;
    cudaDeviceGetAttribute(&nsm, cudaDevAttrMultiProcessorCount, 0);
    int grid = 2 * nsm;
    if (grid > NT) grid = NT;

    moe_mma_kernel<<<grid, 128>>>(x, W1, b1, W2, b2, W3, b3,
                                  Wg1, bg1, Wg2, bg2, out, B, NT);
}

// round 11
// speedup vs baseline: 2.8117x; 2.8117x over previous
#include <cuda_runtime.h>
#include <cuda_fp16.h>
#include <cstdint>

// MoE dense 8-expert: D_IN=6, H=32, D_OUT=2, B=1M, fp32.
// R11 = R7 structure, pure fp16 MMA (no split residuals at all).
//  - layer-1: ONE m16n8k8 per (nf,mf): x_fp16 @ W1_fp16, b1 in k=6 slot, C=0.
//  - layer-2: TWO m16n8k16 per (nf,mf) (K=32), b2 via C-operand on the first.
//  - dropped fp16 rounding terms: ~1e-4 each (R10 measured 1.6e-4 for one);
//    predicted total rel_err ~3e-4 < 1e-3.
// Gate scalar FFMA2 + SHFL, 32 tok/warp, grid = 2 CTAs/SM (R7 proven config).

#define ED 8
#define DI 6
#define HH 32
#define DO 2

typedef unsigned long long u64;
typedef unsigned int u32;

// ---- scalar helpers ----
__device__ __forceinline__ void ffma2_acc(u64& acc, u64 a, u64 b) {
    asm("fma.rn.f32x2 %0, %1, %2, %0;" : "+l"(acc) : "l"(a), "l"(b));
}
__device__ __forceinline__ u64 pack_dup(float v) {
    u64 r; asm("mov.b64 %0, {%1, %1};" : "=l"(r) : "r"(__float_as_uint(v))); return r;
}
__device__ __forceinline__ float2 unpack2(u64 v) {
    float2 f; asm("mov.b64 {%0, %1}, %2;" : "=f"(f.x), "=f"(f.y) : "l"(v)); return f;
}
// pack two f32 -> f16x2 (element0 = lo_e arg, element1 = hi_e arg)
__device__ __forceinline__ u32 f16x2_of(float lo_e, float hi_e) {
    u32 r; asm("cvt.rn.f16x2.f32 %0, %1, %2;" : "=r"(r) : "f"(hi_e), "f"(lo_e)); return r;
}

// ---- MMA helpers (fp16 in, fp32 accum) ----
__device__ __forceinline__ void mma_f16(float& d0, float& d1, float& d2, float& d3,
                                        u32 a0, u32 a1, u32 a2, u32 a3,
                                        u32 b0, u32 b1) {
    asm("mma.sync.aligned.m16n8k16.row.col.f32.f16.f16.f32 "
        "{%0,%1,%2,%3}, {%4,%5,%6,%7}, {%8,%9}, {%0,%1,%2,%3};"
        : "+f"(d0), "+f"(d1), "+f"(d2), "+f"(d3)
        : "r"(a0), "r"(a1), "r"(a2), "r"(a3), "r"(b0), "r"(b1));
}
__device__ __forceinline__ void mma_f16_c(float& d0, float& d1, float& d2, float& d3,
                                          u32 a0, u32 a1, u32 a2, u32 a3,
                                          u32 b0, u32 b1,
                                          float c0, float c1, float c2, float c3) {
    asm("mma.sync.aligned.m16n8k16.row.col.f32.f16.f16.f32 "
        "{%0,%1,%2,%3}, {%4,%5,%6,%7}, {%8,%9}, {%10,%11,%12,%13};"
        : "=f"(d0), "=f"(d1), "=f"(d2), "=f"(d3)
        : "r"(a0), "r"(a1), "r"(a2), "r"(a3), "r"(b0), "r"(b1),
          "f"(c0), "f"(c1), "f"(c2), "f"(c3));
}
__device__ __forceinline__ void mma_f16_k8_c(float& d0, float& d1, float& d2, float& d3,
                                             u32 a0, u32 a1, u32 b0,
                                             float c0, float c1, float c2, float c3) {
    asm("mma.sync.aligned.m16n8k8.row.col.f32.f16.f16.f32 "
        "{%0,%1,%2,%3}, {%4,%5}, {%6}, {%7,%8,%9,%10};"
        : "=f"(d0), "=f"(d1), "=f"(d2), "=f"(d3)
        : "r"(a0), "r"(a1), "r"(b0),
          "f"(c0), "f"(c1), "f"(c2), "f"(c3));
}

__global__ __launch_bounds__(128)
void moe_mma_kernel(const float* __restrict__ gx,
                    const float* __restrict__ gW1, const float* __restrict__ gb1,
                    const float* __restrict__ gW2, const float* __restrict__ gb2,
                    const float* __restrict__ gW3, const float* __restrict__ gb3,
                    const float* __restrict__ gWg1, const float* __restrict__ gbg1,
                    const float* __restrict__ gWg2, const float* __restrict__ gbg2,
                    float* __restrict__ gout, int B, int NT)
{
    __shared__ __align__(16) float sx[4 * 192];               // per-warp x tiles
    __shared__ __align__(16) char  sBfrag[ED * 4 * 32 * 16];  // layer-2 W2 fp16 frags
    __shared__ __align__(16) char  sB1frag[ED * 32 * 16];     // layer-1 W1 fp16 frags, b1 @k=6
    __shared__ __align__(16) float sb2[ED * HH];
    __shared__ __align__(16) float sW3[ED * HH * DO];
    __shared__ __align__(16) float sb3[ED * DO];
    __shared__ __align__(16) float sWg1[DI * HH];
    __shared__ __align__(16) float sbg1[HH];
    __shared__ __align__(16) float sWg2[HH * ED];
    __shared__ __align__(16) float sbg2[ED];

    const int tid  = threadIdx.x;
    const int w    = tid >> 5;
    const int lane = tid & 31;
    const int g    = lane >> 2;   // groupID
    const int q    = lane & 3;    // threadID in group

    // ---- stage small weights ----
    for (int i = tid; i < ED * HH;      i += 128) sb2[i]  = gb2[i];
    for (int i = tid; i < ED * HH * DO; i += 128) sW3[i]  = gW3[i];
    for (int i = tid; i < ED * DO;      i += 128) sb3[i]  = gb3[i];
    for (int i = tid; i < DI * HH;      i += 128) sWg1[i] = gWg1[i];
    for (int i = tid; i < HH;           i += 128) sbg1[i] = gbg1[i];
    for (int i = tid; i < HH * ED;      i += 128) sWg2[i] = gWg2[i];
    for (int i = tid; i < ED;           i += 128) sbg2[i] = gbg2[i];

    // ---- precompute per-lane B fragments (fp16, hi only) ----
    for (int e = w * 2; e < w * 2 + 2; e++) {
        // layer-2: chunk c = kf*2 + nf_half; lane pair (k=16kf+2q,+1) and (+8,+9)
        #pragma unroll
        for (int c = 0; c < 4; c++) {
            const int kf = c >> 1, nfh = c & 1;
            u32 hi4[4];
            #pragma unroll
            for (int p = 0; p < 2; p++) {
                const int n  = (nfh * 2 + p) * 8 + g;
                const int k0 = kf * 16 + 2 * q;
                hi4[p * 2 + 0] = f16x2_of(gW2[e * 1024 + (k0    ) * 32 + n],
                                          gW2[e * 1024 + (k0 + 1) * 32 + n]);
                hi4[p * 2 + 1] = f16x2_of(gW2[e * 1024 + (k0 + 8) * 32 + n],
                                          gW2[e * 1024 + (k0 + 9) * 32 + n]);
            }
            *(uint4*)(sBfrag + ((e * 4 + c) * 32 + lane) * 16) = make_uint4(hi4[0], hi4[1], hi4[2], hi4[3]);
        }
        // layer-1 (k8 frag; q==3 carries b1 at k=6, 0 at k=7)
        {
            u32 hi4[4];
            #pragma unroll
            for (int nf = 0; nf < 4; nf++) {
                const int n = nf * 8 + g;
                float w0, w1;
                if (q < 3) {
                    w0 = gW1[e * 192 + (2 * q    ) * 32 + n];
                    w1 = gW1[e * 192 + (2 * q + 1) * 32 + n];
                } else {
                    w0 = gb1[e * 32 + n];   // k=6: bias (A supplies 1.0)
                    w1 = 0.0f;              // k=7: unused
                }
                hi4[nf] = f16x2_of(w0, w1);
            }
            *(uint4*)(sB1frag + (e * 32 + lane) * 16) = make_uint4(hi4[0], hi4[1], hi4[2], hi4[3]);
        }
    }
    __syncthreads();

    const int lim6 = B * DI;
    const float fz = 0.0f;

    // ---- persistent per-warp tile loop (32 tokens per warp) ----
    for (int tile = blockIdx.x; tile < NT; tile += gridDim.x) {
        const int base = tile * 128 + w * 32;
        float* sxw = sx + w * 192;
        #pragma unroll
        for (int i = 0; i < 6; i++) {
            const int idx = base * DI + i * 32 + lane;
            sxw[i * 32 + lane] = (idx < lim6) ? gx[idx] : 0.0f;
        }
        __syncwarp();

        // ---- x A-fragments (fp16, k8 layout); q==3 -> 1.0 bias slot ----
        u32 xhi[2][2];
        #pragma unroll
        for (int mf = 0; mf < 2; mf++) {
            const int r0 = 16 * mf + g, r1 = r0 + 8;
            float v00, v01, v10, v11;
            if (q < 3) {
                v00 = sxw[r0 * DI + 2 * q]; v01 = sxw[r0 * DI + 2 * q + 1];
                v10 = sxw[r1 * DI + 2 * q]; v11 = sxw[r1 * DI + 2 * q + 1];
            } else {
                v00 = 1.0f; v01 = 0.0f; v10 = 1.0f; v11 = 0.0f;
            }
            xhi[mf][0] = f16x2_of(v00, v01);
            xhi[mf][1] = f16x2_of(v10, v11);
        }

        // ---- gate for token (g + 8q): packed FFMA2 (fp32 exact) ----
        float gg[ED];
        {
            const float* xg = sxw + (g + 8 * q) * DI;
            u64 gacc[HH / 2];
            const u64* bg1p = (const u64*)sbg1;
            #pragma unroll
            for (int i = 0; i < HH / 2; i++) gacc[i] = bg1p[i];
            #pragma unroll
            for (int d = 0; d < DI; d++) {
                const u64 xd = pack_dup(xg[d]);
                const u64* wr = (const u64*)(sWg1 + d * HH);
                #pragma unroll
                for (int i = 0; i < HH / 2; i++) ffma2_acc(gacc[i], xd, wr[i]);
            }
            u64 lacc[ED / 2];
            const u64* bg2p = (const u64*)sbg2;
            #pragma unroll
            for (int i = 0; i < ED / 2; i++) lacc[i] = bg2p[i];
            #pragma unroll
            for (int i = 0; i < HH / 2; i++) {
                const float2 t = unpack2(gacc[i]);
                const u64 hj0 = pack_dup(fmaxf(t.x, 0.0f));
                const u64 hj1 = pack_dup(fmaxf(t.y, 0.0f));
                const u64* wr0 = (const u64*)(sWg2 + (2 * i    ) * ED);
                const u64* wr1 = (const u64*)(sWg2 + (2 * i + 1) * ED);
                #pragma unroll
                for (int k2 = 0; k2 < ED / 2; k2++) {
                    ffma2_acc(lacc[k2], hj0, wr0[k2]);
                    ffma2_acc(lacc[k2], hj1, wr1[k2]);
                }
            }
            float lg[ED];
            #pragma unroll
            for (int i = 0; i < ED / 2; i++) {
                const float2 t = unpack2(lacc[i]);
                lg[2 * i] = t.x; lg[2 * i + 1] = t.y;
            }
            float mx = lg[0];
            #pragma unroll
            for (int e = 1; e < ED; e++) mx = fmaxf(mx, lg[e]);
            float s = 0.0f;
            #pragma unroll
            for (int e = 0; e < ED; e++) { lg[e] = __expf(lg[e] - mx); s += lg[e]; }
            const float inv = 1.0f / s;
            #pragma unroll
            for (int e = 0; e < ED; e++) gg[e] = lg[e] * inv;
        }

        float2 oP[4];
        #pragma unroll
        for (int m = 0; m < 4; m++) oP[m] = make_float2(0.0f, 0.0f);

        // ---- experts ----
        #pragma unroll
        for (int e = 0; e < ED; e++) {
            const uint4 b1f = *(const uint4*)(sB1frag + (e * 32 + lane) * 16);
            uint4 cH[4];
            #pragma unroll
            for (int c = 0; c < 4; c++)
                cH[c] = *(const uint4*)(sBfrag + ((e * 4 + c) * 32 + lane) * 16);

            // layer 1: ONE k8 MMA per (nf,mf): h1 = x @ W1 (+b1 at k=6), C=0
            float h1d[2][4][4];
            #pragma unroll
            for (int nf = 0; nf < 4; nf++) {
                const u32 bh = (nf == 0) ? b1f.x : (nf == 1) ? b1f.y : (nf == 2) ? b1f.z : b1f.w;
                #pragma unroll
                for (int mf = 0; mf < 2; mf++) {
                    mma_f16_k8_c(h1d[mf][nf][0], h1d[mf][nf][1], h1d[mf][nf][2], h1d[mf][nf][3],
                                 xhi[mf][0], xhi[mf][1], bh, fz, fz, fz, fz);
                }
            }

            // relu + fp16 pack: D n-frag nf -> layer-2 A (kf = nf>>1, half = nf&1)
            u32 ahi[2][2][4];   // [mf][kf][reg]
            #pragma unroll
            for (int mf = 0; mf < 2; mf++) {
                #pragma unroll
                for (int nf = 0; nf < 4; nf++) {
                    const float f0 = fmaxf(h1d[mf][nf][0], 0.0f);
                    const float f1 = fmaxf(h1d[mf][nf][1], 0.0f);
                    const float f2 = fmaxf(h1d[mf][nf][2], 0.0f);
                    const float f3 = fmaxf(h1d[mf][nf][3], 0.0f);
                    const int kf = nf >> 1, half = nf & 1;
                    ahi[mf][kf][half * 2 + 0] = f16x2_of(f0, f1);   // row g
                    ahi[mf][kf][half * 2 + 1] = f16x2_of(f2, f3);   // row g+8
                }
            }

            // b2 / W3 fragments
            float2 b2p[4]; float4 w34[4];
            #pragma unroll
            for (int nf = 0; nf < 4; nf++) {
                b2p[nf] = *(const float2*)&sb2[e * HH + nf * 8 + 2 * q];
                w34[nf] = *(const float4*)&sW3[(e * HH + nf * 8 + 2 * q) * DO];
            }

            // layer-2: TWO k16 MMAs per (nf,mf); b2 via C on the first
            float dd[2][4][4];
            #pragma unroll
            for (int nf = 0; nf < 4; nf++) {
                const uint4 h40 = cH[0 * 2 + (nf >> 1)];
                const uint4 h41 = cH[1 * 2 + (nf >> 1)];
                const u32 b0k0 = (nf & 1) ? h40.z : h40.x;
                const u32 b1k0 = (nf & 1) ? h40.w : h40.y;
                const u32 b0k1 = (nf & 1) ? h41.z : h41.x;
                const u32 b1k1 = (nf & 1) ? h41.w : h41.y;
                #pragma unroll
                for (int mf = 0; mf < 2; mf++) {
                    mma_f16_c(dd[mf][nf][0], dd[mf][nf][1], dd[mf][nf][2], dd[mf][nf][3],
                              ahi[mf][0][0], ahi[mf][0][1], ahi[mf][0][2], ahi[mf][0][3],
                              b0k0, b1k0,
                              b2p[nf].x, b2p[nf].y, b2p[nf].x, b2p[nf].y);
                    mma_f16(dd[mf][nf][0], dd[mf][nf][1], dd[mf][nf][2], dd[mf][nf][3],
                            ahi[mf][1][0], ahi[mf][1][1], ahi[mf][1][2], ahi[mf][1][3],
                            b0k1, b1k1);
                }
            }

            // epilogue: relu + layer3 + gate-weighted accumulate
            const float y0b = sb3[e * DO + 0];
            const float y1b = sb3[e * DO + 1];
            #pragma unroll
            for (int m = 0; m < 4; m++) {
                const int mf = m >> 1, r = m & 1;
                float y0 = y0b, y1 = y1b;
                #pragma unroll
                for (int nf = 0; nf < 4; nf++) {
                    const float ha = fmaxf(dd[mf][nf][r * 2 + 0], 0.0f);
                    const float hb = fmaxf(dd[mf][nf][r * 2 + 1], 0.0f);
                    y0 = fmaf(ha, w34[nf].x, y0);
                    y1 = fmaf(ha, w34[nf].y, y1);
                    y0 = fmaf(hb, w34[nf].z, y0);
                    y1 = fmaf(hb, w34[nf].w, y1);
                }
                const float ge = __shfl_sync(0xffffffffu, gg[e], (lane & 28) + m);
                oP[m].x = fmaf(ge, y0, oP[m].x);
                oP[m].y = fmaf(ge, y1, oP[m].y);
            }
        }

        // ---- quad butterfly reduction, write own token ----
        #pragma unroll
        for (int m = 0; m < 4; m++) {
            #pragma unroll
            for (int o = 1; o <= 2; o <<= 1) {
                oP[m].x += __shfl_xor_sync(0xffffffffu, oP[m].x, o);
                oP[m].y += __shfl_xor_sync(0xffffffffu, oP[m].y, o);
            }
        }
        float2 res = oP[0];
        if (q == 1) res = oP[1];
        if (q == 2) res = oP[2];
        if (q == 3) res = oP[3];
        const int t = base + g + 8 * q;
        if (t < B) ((float2*)gout)[t] = res;
    }
}

extern "C" void kernel_launch(void* const* d_in, const int* in_sizes, int n_in,
                              void* d_out, int out_size)
{
    const float* x   = (const float*)d_in[0];
    const float* W1  = (const float*)d_in[1];
    const float* b1  = (const float*)d_in[2];
    const float* W2  = (const float*)d_in[3];
    const float* b2  = (const float*)d_in[4];
    const float* W3  = (const float*)d_in[5];
    const float* b3  = (const float*)d_in[6];
    const float* Wg1 = (const float*)d_in[7];
    const float* bg1 = (const float*)d_in[8];
    const float* Wg2 = (const float*)d_in[9];
    const float* bg2 = (const float*)d_in[10];
    float* out = (float*)d_out;

    const int B  = in_sizes[0] / DI;
    const int NT = (B + 127) / 128;

    int nsm = 148;
    cudaDeviceGetAttribute(&nsm, cudaDevAttrMultiProcessorCount, 0);
    int grid = 2 * nsm;
    if (grid > NT) grid = NT;

    moe_mma_kernel<<<grid, 128>>>(x, W1, b1, W2, b2, W3, b3,
                                  Wg1, bg1, Wg2, bg2, out, B, NT);
}

// round 12
// speedup vs baseline: 3.1942x; 1.1360x over previous
#include <cuda_runtime.h>
#include <cuda_fp16.h>
#include <cstdint>

// MoE dense 8-expert: D_IN=6, H=32, D_OUT=2, B=1M, fp32.
// R12 = R11 (pure fp16 mma both expert layers) + MMA-ized GATE:
//  - gate layer-1 reuses the x A-fragments (1.0 @k=6) with a Wg1 frag
//    carrying bg1 @k=6 -> 8 k8 MMAs.
//  - gate layer-2: H=32 -> E=8 is native m16n8k16 N=8 -> 4 k16 MMAs,
//    bg2 via C-operand.
//  - softmax cross-lane via quad butterflies; epilogue gate fetch via shfl
//    from quad-lane (e>>1), element (e&1).
// Removes ~240 broadcast LDS + ~240 FFMA2 per warp-tile (the measured L1 59%
// hotspot). Grid = 2 CTAs/SM, 32 tok/warp.

#define ED 8
#define DI 6
#define HH 32
#define DO 2

typedef unsigned int u32;

// pack two f32 -> f16x2 (element0 = lo_e arg, element1 = hi_e arg)
__device__ __forceinline__ u32 f16x2_of(float lo_e, float hi_e) {
    u32 r; asm("cvt.rn.f16x2.f32 %0, %1, %2;" : "=r"(r) : "f"(hi_e), "f"(lo_e)); return r;
}

// ---- MMA helpers (fp16 in, fp32 accum) ----
__device__ __forceinline__ void mma_f16(float& d0, float& d1, float& d2, float& d3,
                                        u32 a0, u32 a1, u32 a2, u32 a3,
                                        u32 b0, u32 b1) {
    asm("mma.sync.aligned.m16n8k16.row.col.f32.f16.f16.f32 "
        "{%0,%1,%2,%3}, {%4,%5,%6,%7}, {%8,%9}, {%0,%1,%2,%3};"
        : "+f"(d0), "+f"(d1), "+f"(d2), "+f"(d3)
        : "r"(a0), "r"(a1), "r"(a2), "r"(a3), "r"(b0), "r"(b1));
}
__device__ __forceinline__ void mma_f16_c(float& d0, float& d1, float& d2, float& d3,
                                          u32 a0, u32 a1, u32 a2, u32 a3,
                                          u32 b0, u32 b1,
                                          float c0, float c1, float c2, float c3) {
    asm("mma.sync.aligned.m16n8k16.row.col.f32.f16.f16.f32 "
        "{%0,%1,%2,%3}, {%4,%5,%6,%7}, {%8,%9}, {%10,%11,%12,%13};"
        : "=f"(d0), "=f"(d1), "=f"(d2), "=f"(d3)
        : "r"(a0), "r"(a1), "r"(a2), "r"(a3), "r"(b0), "r"(b1),
          "f"(c0), "f"(c1), "f"(c2), "f"(c3));
}
__device__ __forceinline__ void mma_f16_k8_c(float& d0, float& d1, float& d2, float& d3,
                                             u32 a0, u32 a1, u32 b0,
                                             float c0, float c1, float c2, float c3) {
    asm("mma.sync.aligned.m16n8k8.row.col.f32.f16.f16.f32 "
        "{%0,%1,%2,%3}, {%4,%5}, {%6}, {%7,%8,%9,%10};"
        : "=f"(d0), "=f"(d1), "=f"(d2), "=f"(d3)
        : "r"(a0), "r"(a1), "r"(b0),
          "f"(c0), "f"(c1), "f"(c2), "f"(c3));
}

__global__ __launch_bounds__(128)
void moe_mma_kernel(const float* __restrict__ gx,
                    const float* __restrict__ gW1, const float* __restrict__ gb1,
                    const float* __restrict__ gW2, const float* __restrict__ gb2,
                    const float* __restrict__ gW3, const float* __restrict__ gb3,
                    const float* __restrict__ gWg1, const float* __restrict__ gbg1,
                    const float* __restrict__ gWg2, const float* __restrict__ gbg2,
                    float* __restrict__ gout, int B, int NT)
{
    __shared__ __align__(16) float sx[4 * 192];               // per-warp x tiles
    __shared__ __align__(16) char  sBfrag[ED * 4 * 32 * 16];  // layer-2 W2 fp16 frags
    __shared__ __align__(16) char  sB1frag[ED * 32 * 16];     // layer-1 W1 fp16 frags, b1 @k=6
    __shared__ __align__(16) char  sG1frag[32 * 16];          // gate Wg1 frag, bg1 @k=6
    __shared__ __align__(16) char  sG2frag[32 * 16];          // gate Wg2 frag (K=32, N=8)
    __shared__ __align__(16) float sb2[ED * HH];
    __shared__ __align__(16) float sW3[ED * HH * DO];
    __shared__ __align__(16) float sb3[ED * DO];

    const int tid  = threadIdx.x;
    const int w    = tid >> 5;
    const int lane = tid & 31;
    const int g    = lane >> 2;   // groupID
    const int q    = lane & 3;    // threadID in group

    // ---- stage small weights ----
    for (int i = tid; i < ED * HH;      i += 128) sb2[i] = gb2[i];
    for (int i = tid; i < ED * HH * DO; i += 128) sW3[i] = gW3[i];
    for (int i = tid; i < ED * DO;      i += 128) sb3[i] = gb3[i];

    // ---- precompute per-lane B fragments (fp16) ----
    for (int e = w * 2; e < w * 2 + 2; e++) {
        // layer-2: chunk c = kf*2 + nf_half; lane pair (k=16kf+2q,+1) and (+8,+9), n = ..*8+g
        #pragma unroll
        for (int c = 0; c < 4; c++) {
            const int kf = c >> 1, nfh = c & 1;
            u32 hi4[4];
            #pragma unroll
            for (int p = 0; p < 2; p++) {
                const int n  = (nfh * 2 + p) * 8 + g;
                const int k0 = kf * 16 + 2 * q;
                hi4[p * 2 + 0] = f16x2_of(gW2[e * 1024 + (k0    ) * 32 + n],
                                          gW2[e * 1024 + (k0 + 1) * 32 + n]);
                hi4[p * 2 + 1] = f16x2_of(gW2[e * 1024 + (k0 + 8) * 32 + n],
                                          gW2[e * 1024 + (k0 + 9) * 32 + n]);
            }
            *(uint4*)(sBfrag + ((e * 4 + c) * 32 + lane) * 16) = make_uint4(hi4[0], hi4[1], hi4[2], hi4[3]);
        }
        // layer-1 (k8 frag; q==3 carries b1 at k=6, 0 at k=7)
        {
            u32 hi4[4];
            #pragma unroll
            for (int nf = 0; nf < 4; nf++) {
                const int n = nf * 8 + g;
                float w0, w1;
                if (q < 3) {
                    w0 = gW1[e * 192 + (2 * q    ) * 32 + n];
                    w1 = gW1[e * 192 + (2 * q + 1) * 32 + n];
                } else {
                    w0 = gb1[e * 32 + n];
                    w1 = 0.0f;
                }
                hi4[nf] = f16x2_of(w0, w1);
            }
            *(uint4*)(sB1frag + (e * 32 + lane) * 16) = make_uint4(hi4[0], hi4[1], hi4[2], hi4[3]);
        }
    }
    // gate layer-1 frag (same layout as expert layer-1; bg1 @k=6)
    if (w == 0) {
        u32 hi4[4];
        #pragma unroll
        for (int nf = 0; nf < 4; nf++) {
            const int n = nf * 8 + g;
            float w0, w1;
            if (q < 3) {
                w0 = gWg1[(2 * q    ) * 32 + n];
                w1 = gWg1[(2 * q + 1) * 32 + n];
            } else {
                w0 = gbg1[n];
                w1 = 0.0f;
            }
            hi4[nf] = f16x2_of(w0, w1);
        }
        *(uint4*)(sG1frag + lane * 16) = make_uint4(hi4[0], hi4[1], hi4[2], hi4[3]);
    }
    // gate layer-2 frag: K=32 (two k16 chunks), N=8 (n = g); Wg2 is [HH, ED]
    if (w == 1) {
        u32 f4[4];
        #pragma unroll
        for (int kf = 0; kf < 2; kf++) {
            const int k0 = kf * 16 + 2 * q;
            f4[kf * 2 + 0] = f16x2_of(gWg2[(k0    ) * ED + g], gWg2[(k0 + 1) * ED + g]);
            f4[kf * 2 + 1] = f16x2_of(gWg2[(k0 + 8) * ED + g], gWg2[(k0 + 9) * ED + g]);
        }
        *(uint4*)(sG2frag + lane * 16) = make_uint4(f4[0], f4[1], f4[2], f4[3]);
    }
    __syncthreads();

    const int lim6 = B * DI;
    const float fz = 0.0f;
    const float2 bg2c = ((const float2*)gbg2)[q];   // C-operand cols 2q, 2q+1

    // ---- persistent per-warp tile loop (32 tokens per warp) ----
    for (int tile = blockIdx.x; tile < NT; tile += gridDim.x) {
        const int base = tile * 128 + w * 32;
        float* sxw = sx + w * 192;
        #pragma unroll
        for (int i = 0; i < 6; i++) {
            const int idx = base * DI + i * 32 + lane;
            sxw[i * 32 + lane] = (idx < lim6) ? gx[idx] : 0.0f;
        }
        __syncwarp();

        // ---- x A-fragments (fp16, k8 layout); q==3 -> 1.0 bias slot ----
        u32 xhi[2][2];
        #pragma unroll
        for (int mf = 0; mf < 2; mf++) {
            const int r0 = 16 * mf + g, r1 = r0 + 8;
            float v00, v01, v10, v11;
            if (q < 3) {
                v00 = sxw[r0 * DI + 2 * q]; v01 = sxw[r0 * DI + 2 * q + 1];
                v10 = sxw[r1 * DI + 2 * q]; v11 = sxw[r1 * DI + 2 * q + 1];
            } else {
                v00 = 1.0f; v01 = 0.0f; v10 = 1.0f; v11 = 0.0f;
            }
            xhi[mf][0] = f16x2_of(v00, v01);
            xhi[mf][1] = f16x2_of(v10, v11);
        }

        // ---- GATE via MMA + quad-butterfly softmax ----
        // glane[m][j] = softmax gate for (row g+8m, expert 2q+j)
        float glane[4][2];
        {
            const uint4 g1f = *(const uint4*)(sG1frag + lane * 16);
            float hgd[2][4][4];
            #pragma unroll
            for (int nf = 0; nf < 4; nf++) {
                const u32 bh = (nf == 0) ? g1f.x : (nf == 1) ? g1f.y : (nf == 2) ? g1f.z : g1f.w;
                #pragma unroll
                for (int mf = 0; mf < 2; mf++) {
                    mma_f16_k8_c(hgd[mf][nf][0], hgd[mf][nf][1], hgd[mf][nf][2], hgd[mf][nf][3],
                                 xhi[mf][0], xhi[mf][1], bh, fz, fz, fz, fz);
                }
            }
            // relu + pack hgate -> A-frags for gate layer-2 (K=32)
            u32 ag[2][2][4];
            #pragma unroll
            for (int mf = 0; mf < 2; mf++) {
                #pragma unroll
                for (int nf = 0; nf < 4; nf++) {
                    const float f0 = fmaxf(hgd[mf][nf][0], 0.0f);
                    const float f1 = fmaxf(hgd[mf][nf][1], 0.0f);
                    const float f2 = fmaxf(hgd[mf][nf][2], 0.0f);
                    const float f3 = fmaxf(hgd[mf][nf][3], 0.0f);
                    const int kf = nf >> 1, half = nf & 1;
                    ag[mf][kf][half * 2 + 0] = f16x2_of(f0, f1);
                    ag[mf][kf][half * 2 + 1] = f16x2_of(f2, f3);
                }
            }
            const uint4 g2f = *(const uint4*)(sG2frag + lane * 16);
            float gl[2][4];
            #pragma unroll
            for (int mf = 0; mf < 2; mf++) {
                mma_f16_c(gl[mf][0], gl[mf][1], gl[mf][2], gl[mf][3],
                          ag[mf][0][0], ag[mf][0][1], ag[mf][0][2], ag[mf][0][3],
                          g2f.x, g2f.y,
                          bg2c.x, bg2c.y, bg2c.x, bg2c.y);
                mma_f16(gl[mf][0], gl[mf][1], gl[mf][2], gl[mf][3],
                        ag[mf][1][0], ag[mf][1][1], ag[mf][1][2], ag[mf][1][3],
                        g2f.z, g2f.w);
            }
            // softmax per row (quad holds the 8 experts: 2 per lane)
            #pragma unroll
            for (int mf = 0; mf < 2; mf++) {
                #pragma unroll
                for (int r = 0; r < 2; r++) {
                    const int m = 2 * mf + r;
                    const float l0 = gl[mf][r * 2 + 0];
                    const float l1 = gl[mf][r * 2 + 1];
                    float mx = fmaxf(l0, l1);
                    mx = fmaxf(mx, __shfl_xor_sync(0xffffffffu, mx, 1));
                    mx = fmaxf(mx, __shfl_xor_sync(0xffffffffu, mx, 2));
                    const float e0 = __expf(l0 - mx);
                    const float e1 = __expf(l1 - mx);
                    float s = e0 + e1;
                    s += __shfl_xor_sync(0xffffffffu, s, 1);
                    s += __shfl_xor_sync(0xffffffffu, s, 2);
                    const float inv = 1.0f / s;
                    glane[m][0] = e0 * inv;
                    glane[m][1] = e1 * inv;
                }
            }
        }

        float2 oP[4];
        #pragma unroll
        for (int m = 0; m < 4; m++) oP[m] = make_float2(0.0f, 0.0f);

        // ---- experts ----
        #pragma unroll
        for (int e = 0; e < ED; e++) {
            const uint4 b1f = *(const uint4*)(sB1frag + (e * 32 + lane) * 16);
            uint4 cH[4];
            #pragma unroll
            for (int c = 0; c < 4; c++)
                cH[c] = *(const uint4*)(sBfrag + ((e * 4 + c) * 32 + lane) * 16);

            // layer 1: ONE k8 MMA per (nf,mf): h1 = x @ W1 (+b1 at k=6), C=0
            float h1d[2][4][4];
            #pragma unroll
            for (int nf = 0; nf < 4; nf++) {
                const u32 bh = (nf == 0) ? b1f.x : (nf == 1) ? b1f.y : (nf == 2) ? b1f.z : b1f.w;
                #pragma unroll
                for (int mf = 0; mf < 2; mf++) {
                    mma_f16_k8_c(h1d[mf][nf][0], h1d[mf][nf][1], h1d[mf][nf][2], h1d[mf][nf][3],
                                 xhi[mf][0], xhi[mf][1], bh, fz, fz, fz, fz);
                }
            }

            // relu + fp16 pack: D n-frag nf -> layer-2 A (kf = nf>>1, half = nf&1)
            u32 ahi[2][2][4];
            #pragma unroll
            for (int mf = 0; mf < 2; mf++) {
                #pragma unroll
                for (int nf = 0; nf < 4; nf++) {
                    const float f0 = fmaxf(h1d[mf][nf][0], 0.0f);
                    const float f1 = fmaxf(h1d[mf][nf][1], 0.0f);
                    const float f2 = fmaxf(h1d[mf][nf][2], 0.0f);
                    const float f3 = fmaxf(h1d[mf][nf][3], 0.0f);
                    const int kf = nf >> 1, half = nf & 1;
                    ahi[mf][kf][half * 2 + 0] = f16x2_of(f0, f1);
                    ahi[mf][kf][half * 2 + 1] = f16x2_of(f2, f3);
                }
            }

            // b2 / W3 fragments
            float2 b2p[4]; float4 w34[4];
            #pragma unroll
            for (int nf = 0; nf < 4; nf++) {
                b2p[nf] = *(const float2*)&sb2[e * HH + nf * 8 + 2 * q];
                w34[nf] = *(const float4*)&sW3[(e * HH + nf * 8 + 2 * q) * DO];
            }

            // layer-2: TWO k16 MMAs per (nf,mf); b2 via C on the first
            float dd[2][4][4];
            #pragma unroll
            for (int nf = 0; nf < 4; nf++) {
                const uint4 h40 = cH[0 * 2 + (nf >> 1)];
                const uint4 h41 = cH[1 * 2 + (nf >> 1)];
                const u32 b0k0 = (nf & 1) ? h40.z : h40.x;
                const u32 b1k0 = (nf & 1) ? h40.w : h40.y;
                const u32 b0k1 = (nf & 1) ? h41.z : h41.x;
                const u32 b1k1 = (nf & 1) ? h41.w : h41.y;
                #pragma unroll
                for (int mf = 0; mf < 2; mf++) {
                    mma_f16_c(dd[mf][nf][0], dd[mf][nf][1], dd[mf][nf][2], dd[mf][nf][3],
                              ahi[mf][0][0], ahi[mf][0][1], ahi[mf][0][2], ahi[mf][0][3],
                              b0k0, b1k0,
                              b2p[nf].x, b2p[nf].y, b2p[nf].x, b2p[nf].y);
                    mma_f16(dd[mf][nf][0], dd[mf][nf][1], dd[mf][nf][2], dd[mf][nf][3],
                            ahi[mf][1][0], ahi[mf][1][1], ahi[mf][1][2], ahi[mf][1][3],
                            b0k1, b1k1);
                }
            }

            // epilogue: relu + layer3 + gate-weighted accumulate
            const float y0b = sb3[e * DO + 0];
            const float y1b = sb3[e * DO + 1];
            #pragma unroll
            for (int m = 0; m < 4; m++) {
                const int mf = m >> 1, r = m & 1;
                float y0 = y0b, y1 = y1b;
                #pragma unroll
                for (int nf = 0; nf < 4; nf++) {
                    const float ha = fmaxf(dd[mf][nf][r * 2 + 0], 0.0f);
                    const float hb = fmaxf(dd[mf][nf][r * 2 + 1], 0.0f);
                    y0 = fmaf(ha, w34[nf].x, y0);
                    y1 = fmaf(ha, w34[nf].y, y1);
                    y0 = fmaf(hb, w34[nf].z, y0);
                    y1 = fmaf(hb, w34[nf].w, y1);
                }
                // gate for (row g+8m, expert e): quad-lane e>>1, element e&1
                const float ge = __shfl_sync(0xffffffffu, glane[m][e & 1], (lane & 28) + (e >> 1));
                oP[m].x = fmaf(ge, y0, oP[m].x);
                oP[m].y = fmaf(ge, y1, oP[m].y);
            }
        }

        // ---- quad butterfly reduction, write own token ----
        #pragma unroll
        for (int m = 0; m < 4; m++) {
            #pragma unroll
            for (int o = 1; o <= 2; o <<= 1) {
                oP[m].x += __shfl_xor_sync(0xffffffffu, oP[m].x, o);
                oP[m].y += __shfl_xor_sync(0xffffffffu, oP[m].y, o);
            }
        }
        float2 res = oP[0];
        if (q == 1) res = oP[1];
        if (q == 2) res = oP[2];
        if (q == 3) res = oP[3];
        const int t = base + g + 8 * q;
        if (t < B) ((float2*)gout)[t] = res;
    }
}

extern "C" void kernel_launch(void* const* d_in, const int* in_sizes, int n_in,
                              void* d_out, int out_size)
{
    const float* x   = (const float*)d_in[0];
    const float* W1  = (const float*)d_in[1];
    const float* b1  = (const float*)d_in[2];
    const float* W2  = (const float*)d_in[3];
    const float* b2  = (const float*)d_in[4];
    const float* W3  = (const float*)d_in[5];
    const float* b3  = (const float*)d_in[6];
    const float* Wg1 = (const float*)d_in[7];
    const float* bg1 = (const float*)d_in[8];
    const float* Wg2 = (const float*)d_in[9];
    const float* bg2 = (const float*)d_in[10];
    float* out = (float*)d_out;

    const int B  = in_sizes[0] / DI;
    const int NT = (B + 127) / 128;

    int nsm = 148;
    cudaDeviceGetAttribute(&nsm, cudaDevAttrMultiProcessorCount, 0);
    int grid = 2 * nsm;
    if (grid > NT) grid = NT;

    moe_mma_kernel<<<grid, 128>>>(x, W1, b1, W2, b2, W3, b3,
                                  Wg1, bg1, Wg2, bg2, out, B, NT);
}

// round 13
// speedup vs baseline: 3.5652x; 1.1162x over previous
#include <cuda_runtime.h>
#include <cuda_fp16.h>
#include <cstdint>

// MoE dense 8-expert: D_IN=6, H=32, D_OUT=2, B=1M, fp32.
// R13 = R12 (fp16 MMA layers 1,2 + MMA gate) with:
//  - layer-3 + gate-mix + cross-quad reduce as MMAs: A = relu(h2)*g_e in fp16
//    (g_e>0 so gate folds into A), B = W3 frags (N=8, cols>=2 zero) hoisted in
//    regs, ONE persistent D accumulated over all 8 experts x 2 kf. Replaces
//    576 FFMA + 32 FMNMX + butterflies per tile.
//  - b3 tail: sum_e g_e*b3_e via packed FFMA2 + 2 quad butterflies per tile.
//  - relu done in fp16 (cvt then max.f16x2 with 0) everywhere: exact same
//    values, fewer alu ops.
// Grid = 2 CTAs/SM, 32 tok/warp.

#define ED 8
#define DI 6
#define HH 32
#define DO 2

typedef unsigned long long u64;
typedef unsigned int u32;

// pack two f32 -> f16x2 (element0 = lo_e arg, element1 = hi_e arg)
__device__ __forceinline__ u32 f16x2_of(float lo_e, float hi_e) {
    u32 r; asm("cvt.rn.f16x2.f32 %0, %1, %2;" : "=r"(r) : "f"(hi_e), "f"(lo_e)); return r;
}
__device__ __forceinline__ u32 hmax2z(u32 a) {
    u32 r; asm("max.f16x2 %0, %1, %2;" : "=r"(r) : "r"(a), "r"(0u)); return r;
}
__device__ __forceinline__ u32 hmul2(u32 a, u32 b) {
    u32 r; asm("mul.f16x2 %0, %1, %2;" : "=r"(r) : "r"(a), "r"(b)); return r;
}
__device__ __forceinline__ void ffma2_acc(u64& acc, u64 a, u64 b) {
    asm("fma.rn.f32x2 %0, %1, %2, %0;" : "+l"(acc) : "l"(a), "l"(b));
}
__device__ __forceinline__ u64 mul2(u64 a, u64 b) {
    u64 r; asm("mul.rn.f32x2 %0, %1, %2;" : "=l"(r) : "l"(a), "l"(b)); return r;
}
__device__ __forceinline__ u64 add2(u64 a, u64 b) {
    u64 r; asm("add.rn.f32x2 %0, %1, %2;" : "=l"(r) : "l"(a), "l"(b)); return r;
}
__device__ __forceinline__ u64 pack_dup(float v) {
    u64 r; asm("mov.b64 %0, {%1, %1};" : "=l"(r) : "r"(__float_as_uint(v))); return r;
}
__device__ __forceinline__ float2 unpack2(u64 v) {
    float2 f; asm("mov.b64 {%0, %1}, %2;" : "=f"(f.x), "=f"(f.y) : "l"(v)); return f;
}

// ---- MMA helpers (fp16 in, fp32 accum) ----
__device__ __forceinline__ void mma_f16(float& d0, float& d1, float& d2, float& d3,
                                        u32 a0, u32 a1, u32 a2, u32 a3,
                                        u32 b0, u32 b1) {
    asm("mma.sync.aligned.m16n8k16.row.col.f32.f16.f16.f32 "
        "{%0,%1,%2,%3}, {%4,%5,%6,%7}, {%8,%9}, {%0,%1,%2,%3};"
        : "+f"(d0), "+f"(d1), "+f"(d2), "+f"(d3)
        : "r"(a0), "r"(a1), "r"(a2), "r"(a3), "r"(b0), "r"(b1));
}
__device__ __forceinline__ void mma_f16_c(float& d0, float& d1, float& d2, float& d3,
                                          u32 a0, u32 a1, u32 a2, u32 a3,
                                          u32 b0, u32 b1,
                                          float c0, float c1, float c2, float c3) {
    asm("mma.sync.aligned.m16n8k16.row.col.f32.f16.f16.f32 "
        "{%0,%1,%2,%3}, {%4,%5,%6,%7}, {%8,%9}, {%10,%11,%12,%13};"
        : "=f"(d0), "=f"(d1), "=f"(d2), "=f"(d3)
        : "r"(a0), "r"(a1), "r"(a2), "r"(a3), "r"(b0), "r"(b1),
          "f"(c0), "f"(c1), "f"(c2), "f"(c3));
}
__device__ __forceinline__ void mma_f16_k8_c(float& d0, float& d1, float& d2, float& d3,
                                             u32 a0, u32 a1, u32 b0,
                                             float c0, float c1, float c2, float c3) {
    asm("mma.sync.aligned.m16n8k8.row.col.f32.f16.f16.f32 "
        "{%0,%1,%2,%3}, {%4,%5}, {%6}, {%7,%8,%9,%10};"
        : "=f"(d0), "=f"(d1), "=f"(d2), "=f"(d3)
        : "r"(a0), "r"(a1), "r"(b0),
          "f"(c0), "f"(c1), "f"(c2), "f"(c3));
}

__global__ __launch_bounds__(128)
void moe_mma_kernel(const float* __restrict__ gx,
                    const float* __restrict__ gW1, const float* __restrict__ gb1,
                    const float* __restrict__ gW2, const float* __restrict__ gb2,
                    const float* __restrict__ gW3, const float* __restrict__ gb3,
                    const float* __restrict__ gWg1, const float* __restrict__ gbg1,
                    const float* __restrict__ gWg2, const float* __restrict__ gbg2,
                    float* __restrict__ gout, int B, int NT)
{
    __shared__ __align__(16) float sx[4 * 192];               // per-warp x tiles
    __shared__ __align__(16) char  sBfrag[ED * 4 * 32 * 16];  // layer-2 W2 fp16 frags
    __shared__ __align__(16) char  sB1frag[ED * 32 * 16];     // layer-1 W1 fp16 frags, b1 @k=6
    __shared__ __align__(16) char  sG1frag[32 * 16];          // gate Wg1 frag, bg1 @k=6
    __shared__ __align__(16) char  sG2frag[32 * 16];          // gate Wg2 frag (K=32, N=8)
    __shared__ __align__(16) float sb2[ED * HH];

    const int tid  = threadIdx.x;
    const int w    = tid >> 5;
    const int lane = tid & 31;
    const int g    = lane >> 2;   // groupID
    const int q    = lane & 3;    // threadID in group

    // ---- stage small weights ----
    for (int i = tid; i < ED * HH; i += 128) sb2[i] = gb2[i];

    // ---- precompute per-lane B fragments (fp16) ----
    for (int e = w * 2; e < w * 2 + 2; e++) {
        // layer-2: chunk c = kf*2 + nf_half
        #pragma unroll
        for (int c = 0; c < 4; c++) {
            const int kf = c >> 1, nfh = c & 1;
            u32 hi4[4];
            #pragma unroll
            for (int p = 0; p < 2; p++) {
                const int n  = (nfh * 2 + p) * 8 + g;
                const int k0 = kf * 16 + 2 * q;
                hi4[p * 2 + 0] = f16x2_of(gW2[e * 1024 + (k0    ) * 32 + n],
                                          gW2[e * 1024 + (k0 + 1) * 32 + n]);
                hi4[p * 2 + 1] = f16x2_of(gW2[e * 1024 + (k0 + 8) * 32 + n],
                                          gW2[e * 1024 + (k0 + 9) * 32 + n]);
            }
            *(uint4*)(sBfrag + ((e * 4 + c) * 32 + lane) * 16) = make_uint4(hi4[0], hi4[1], hi4[2], hi4[3]);
        }
        // layer-1 (k8 frag; q==3 carries b1 at k=6, 0 at k=7)
        {
            u32 hi4[4];
            #pragma unroll
            for (int nf = 0; nf < 4; nf++) {
                const int n = nf * 8 + g;
                float w0, w1;
                if (q < 3) {
                    w0 = gW1[e * 192 + (2 * q    ) * 32 + n];
                    w1 = gW1[e * 192 + (2 * q + 1) * 32 + n];
                } else {
                    w0 = gb1[e * 32 + n];
                    w1 = 0.0f;
                }
                hi4[nf] = f16x2_of(w0, w1);
            }
            *(uint4*)(sB1frag + (e * 32 + lane) * 16) = make_uint4(hi4[0], hi4[1], hi4[2], hi4[3]);
        }
    }
    // gate layer-1 frag (bg1 @k=6)
    if (w == 0) {
        u32 hi4[4];
        #pragma unroll
        for (int nf = 0; nf < 4; nf++) {
            const int n = nf * 8 + g;
            float w0, w1;
            if (q < 3) {
                w0 = gWg1[(2 * q    ) * 32 + n];
                w1 = gWg1[(2 * q + 1) * 32 + n];
            } else {
                w0 = gbg1[n];
                w1 = 0.0f;
            }
            hi4[nf] = f16x2_of(w0, w1);
        }
        *(uint4*)(sG1frag + lane * 16) = make_uint4(hi4[0], hi4[1], hi4[2], hi4[3]);
    }
    // gate layer-2 frag: K=32, N=8 (n=g); Wg2 is [HH, ED]
    if (w == 1) {
        u32 f4[4];
        #pragma unroll
        for (int kf = 0; kf < 2; kf++) {
            const int k0 = kf * 16 + 2 * q;
            f4[kf * 2 + 0] = f16x2_of(gWg2[(k0    ) * ED + g], gWg2[(k0 + 1) * ED + g]);
            f4[kf * 2 + 1] = f16x2_of(gWg2[(k0 + 8) * ED + g], gWg2[(k0 + 9) * ED + g]);
        }
        *(uint4*)(sG2frag + lane * 16) = make_uint4(f4[0], f4[1], f4[2], f4[3]);
    }
    __syncthreads();

    // ---- layer-3 W3 B-fragments, hoisted into registers (K=32, N=8; cols>=2 zero) ----
    // W3 layout [E][H][DO]; lane (g,q): col n=g (valid g<2), k = kf*16 + 2q (+1, +8, +9)
    u32 w3f[ED][4];
    #pragma unroll
    for (int e = 0; e < ED; e++) {
        #pragma unroll
        for (int kf = 0; kf < 2; kf++) {
            const int k0 = kf * 16 + 2 * q;
            u32 b0 = 0, b1 = 0;
            if (g < 2) {
                b0 = f16x2_of(gW3[e * 64 + (k0    ) * DO + g], gW3[e * 64 + (k0 + 1) * DO + g]);
                b1 = f16x2_of(gW3[e * 64 + (k0 + 8) * DO + g], gW3[e * 64 + (k0 + 9) * DO + g]);
            }
            w3f[e][kf * 2 + 0] = b0;
            w3f[e][kf * 2 + 1] = b1;
        }
    }
    // b3 pairs for this lane's two experts (2q, 2q+1), packed f32x2
    const u64 b3q0 = *(const u64*)&gb3[(2 * q    ) * DO];
    const u64 b3q1 = *(const u64*)&gb3[(2 * q + 1) * DO];

    const int lim6 = B * DI;
    const float fz = 0.0f;
    const float2 bg2c = ((const float2*)gbg2)[q];   // gate C-operand cols 2q, 2q+1

    // ---- persistent per-warp tile loop (32 tokens per warp) ----
    for (int tile = blockIdx.x; tile < NT; tile += gridDim.x) {
        const int base = tile * 128 + w * 32;
        float* sxw = sx + w * 192;
        #pragma unroll
        for (int i = 0; i < 6; i++) {
            const int idx = base * DI + i * 32 + lane;
            sxw[i * 32 + lane] = (idx < lim6) ? gx[idx] : 0.0f;
        }
        __syncwarp();

        // ---- x A-fragments (fp16, k8 layout); q==3 -> 1.0 bias slot ----
        u32 xhi[2][2];
        #pragma unroll
        for (int mf = 0; mf < 2; mf++) {
            const int r0 = 16 * mf + g, r1 = r0 + 8;
            float v00, v01, v10, v11;
            if (q < 3) {
                v00 = sxw[r0 * DI + 2 * q]; v01 = sxw[r0 * DI + 2 * q + 1];
                v10 = sxw[r1 * DI + 2 * q]; v11 = sxw[r1 * DI + 2 * q + 1];
            } else {
                v00 = 1.0f; v01 = 0.0f; v10 = 1.0f; v11 = 0.0f;
            }
            xhi[mf][0] = f16x2_of(v00, v01);
            xhi[mf][1] = f16x2_of(v10, v11);
        }

        // ---- GATE via MMA + quad-butterfly softmax ----
        float glane[4][2];   // [m][j]: gate for (row g+8m, expert 2q+j)
        {
            const uint4 g1f = *(const uint4*)(sG1frag + lane * 16);
            float hgd[2][4][4];
            #pragma unroll
            for (int nf = 0; nf < 4; nf++) {
                const u32 bh = (nf == 0) ? g1f.x : (nf == 1) ? g1f.y : (nf == 2) ? g1f.z : g1f.w;
                #pragma unroll
                for (int mf = 0; mf < 2; mf++) {
                    mma_f16_k8_c(hgd[mf][nf][0], hgd[mf][nf][1], hgd[mf][nf][2], hgd[mf][nf][3],
                                 xhi[mf][0], xhi[mf][1], bh, fz, fz, fz, fz);
                }
            }
            u32 ag[2][2][4];
            #pragma unroll
            for (int mf = 0; mf < 2; mf++) {
                #pragma unroll
                for (int nf = 0; nf < 4; nf++) {
                    const int kf = nf >> 1, half = nf & 1;
                    ag[mf][kf][half * 2 + 0] = hmax2z(f16x2_of(hgd[mf][nf][0], hgd[mf][nf][1]));
                    ag[mf][kf][half * 2 + 1] = hmax2z(f16x2_of(hgd[mf][nf][2], hgd[mf][nf][3]));
                }
            }
            const uint4 g2f = *(const uint4*)(sG2frag + lane * 16);
            float gl[2][4];
            #pragma unroll
            for (int mf = 0; mf < 2; mf++) {
                mma_f16_c(gl[mf][0], gl[mf][1], gl[mf][2], gl[mf][3],
                          ag[mf][0][0], ag[mf][0][1], ag[mf][0][2], ag[mf][0][3],
                          g2f.x, g2f.y,
                          bg2c.x, bg2c.y, bg2c.x, bg2c.y);
                mma_f16(gl[mf][0], gl[mf][1], gl[mf][2], gl[mf][3],
                        ag[mf][1][0], ag[mf][1][1], ag[mf][1][2], ag[mf][1][3],
                        g2f.z, g2f.w);
            }
            #pragma unroll
            for (int mf = 0; mf < 2; mf++) {
                #pragma unroll
                for (int r = 0; r < 2; r++) {
                    const int m = 2 * mf + r;
                    const float l0 = gl[mf][r * 2 + 0];
                    const float l1 = gl[mf][r * 2 + 1];
                    float mx = fmaxf(l0, l1);
                    mx = fmaxf(mx, __shfl_xor_sync(0xffffffffu, mx, 1));
                    mx = fmaxf(mx, __shfl_xor_sync(0xffffffffu, mx, 2));
                    const float e0 = __expf(l0 - mx);
                    const float e1 = __expf(l1 - mx);
                    float s = e0 + e1;
                    s += __shfl_xor_sync(0xffffffffu, s, 1);
                    s += __shfl_xor_sync(0xffffffffu, s, 2);
                    const float inv = 1.0f / s;
                    glane[m][0] = e0 * inv;
                    glane[m][1] = e1 * inv;
                }
            }
        }

        // persistent layer-3 accumulator (D over all experts); init via C on e==0
        float acc[2][4];

        // ---- experts ----
        #pragma unroll
        for (int e = 0; e < ED; e++) {
            const uint4 b1f = *(const uint4*)(sB1frag + (e * 32 + lane) * 16);
            uint4 cH[4];
            #pragma unroll
            for (int c = 0; c < 4; c++)
                cH[c] = *(const uint4*)(sBfrag + ((e * 4 + c) * 32 + lane) * 16);

            // layer 1: ONE k8 MMA per (nf,mf)
            float h1d[2][4][4];
            #pragma unroll
            for (int nf = 0; nf < 4; nf++) {
                const u32 bh = (nf == 0) ? b1f.x : (nf == 1) ? b1f.y : (nf == 2) ? b1f.z : b1f.w;
                #pragma unroll
                for (int mf = 0; mf < 2; mf++) {
                    mma_f16_k8_c(h1d[mf][nf][0], h1d[mf][nf][1], h1d[mf][nf][2], h1d[mf][nf][3],
                                 xhi[mf][0], xhi[mf][1], bh, fz, fz, fz, fz);
                }
            }

            // relu in fp16 + pack -> layer-2 A frags
            u32 ahi[2][2][4];
            #pragma unroll
            for (int mf = 0; mf < 2; mf++) {
                #pragma unroll
                for (int nf = 0; nf < 4; nf++) {
                    const int kf = nf >> 1, half = nf & 1;
                    ahi[mf][kf][half * 2 + 0] = hmax2z(f16x2_of(h1d[mf][nf][0], h1d[mf][nf][1]));
                    ahi[mf][kf][half * 2 + 1] = hmax2z(f16x2_of(h1d[mf][nf][2], h1d[mf][nf][3]));
                }
            }

            // b2 bias fragments
            float2 b2p[4];
            #pragma unroll
            for (int nf = 0; nf < 4; nf++)
                b2p[nf] = *(const float2*)&sb2[e * HH + nf * 8 + 2 * q];

            // layer-2: TWO k16 MMAs per (nf,mf); b2 via C on the first
            float dd[2][4][4];
            #pragma unroll
            for (int nf = 0; nf < 4; nf++) {
                const uint4 h40 = cH[0 * 2 + (nf >> 1)];
                const uint4 h41 = cH[1 * 2 + (nf >> 1)];
                const u32 b0k0 = (nf & 1) ? h40.z : h40.x;
                const u32 b1k0 = (nf & 1) ? h40.w : h40.y;
                const u32 b0k1 = (nf & 1) ? h41.z : h41.x;
                const u32 b1k1 = (nf & 1) ? h41.w : h41.y;
                #pragma unroll
                for (int mf = 0; mf < 2; mf++) {
                    mma_f16_c(dd[mf][nf][0], dd[mf][nf][1], dd[mf][nf][2], dd[mf][nf][3],
                              ahi[mf][0][0], ahi[mf][0][1], ahi[mf][0][2], ahi[mf][0][3],
                              b0k0, b1k0,
                              b2p[nf].x, b2p[nf].y, b2p[nf].x, b2p[nf].y);
                    mma_f16(dd[mf][nf][0], dd[mf][nf][1], dd[mf][nf][2], dd[mf][nf][3],
                            ahi[mf][1][0], ahi[mf][1][1], ahi[mf][1][2], ahi[mf][1][3],
                            b0k1, b1k1);
                }
            }

            // gate per row as dup'd half2 (g_e > 0, so relu(h2)*g folds into A)
            u32 geh[4];
            #pragma unroll
            for (int m = 0; m < 4; m++) {
                const float ge = __shfl_sync(0xffffffffu, glane[m][e & 1], (lane & 28) + (e >> 1));
                geh[m] = f16x2_of(ge, ge);
            }

            // layer-3 A frags: relu(dd) in fp16 scaled by gate
            u32 a3[2][2][4];
            #pragma unroll
            for (int mf = 0; mf < 2; mf++) {
                #pragma unroll
                for (int nf = 0; nf < 4; nf++) {
                    const int kf = nf >> 1, half = nf & 1;
                    a3[mf][kf][half * 2 + 0] =
                        hmul2(hmax2z(f16x2_of(dd[mf][nf][0], dd[mf][nf][1])), geh[2 * mf + 0]);
                    a3[mf][kf][half * 2 + 1] =
                        hmul2(hmax2z(f16x2_of(dd[mf][nf][2], dd[mf][nf][3])), geh[2 * mf + 1]);
                }
            }

            // layer-3 MMAs, accumulating across experts (C=0 on very first)
            #pragma unroll
            for (int mf = 0; mf < 2; mf++) {
                if (e == 0) {
                    mma_f16_c(acc[mf][0], acc[mf][1], acc[mf][2], acc[mf][3],
                              a3[mf][0][0], a3[mf][0][1], a3[mf][0][2], a3[mf][0][3],
                              w3f[e][0], w3f[e][1], fz, fz, fz, fz);
                } else {
                    mma_f16(acc[mf][0], acc[mf][1], acc[mf][2], acc[mf][3],
                            a3[mf][0][0], a3[mf][0][1], a3[mf][0][2], a3[mf][0][3],
                            w3f[e][0], w3f[e][1]);
                }
                mma_f16(acc[mf][0], acc[mf][1], acc[mf][2], acc[mf][3],
                        a3[mf][1][0], a3[mf][1][1], a3[mf][1][2], a3[mf][1][3],
                        w3f[e][2], w3f[e][3]);
            }
        }

        // ---- b3 tail: bias[m] = sum_e g[row][e]*b3[e][:], via quad butterflies ----
        u64 bias[4];
        #pragma unroll
        for (int m = 0; m < 4; m++) {
            u64 p = mul2(pack_dup(glane[m][0]), b3q0);
            ffma2_acc(p, pack_dup(glane[m][1]), b3q1);
            p = add2(p, __shfl_xor_sync(0xffffffffu, p, 1));
            p = add2(p, __shfl_xor_sync(0xffffffffu, p, 2));
            bias[m] = p;
        }

        // ---- store: q==0 lanes hold cols 0,1 for rows g+8m ----
        if (q == 0) {
            const float2 bb0 = unpack2(bias[0]);
            const float2 bb1 = unpack2(bias[1]);
            const float2 bb2 = unpack2(bias[2]);
            const float2 bb3 = unpack2(bias[3]);
            const int t0 = base + g;
            if (t0 < B)      ((float2*)gout)[t0]      = make_float2(acc[0][0] + bb0.x, acc[0][1] + bb0.y);
            if (t0 + 8 < B)  ((float2*)gout)[t0 + 8]  = make_float2(acc[0][2] + bb1.x, acc[0][3] + bb1.y);
            if (t0 + 16 < B) ((float2*)gout)[t0 + 16] = make_float2(acc[1][0] + bb2.x, acc[1][1] + bb2.y);
            if (t0 + 24 < B) ((float2*)gout)[t0 + 24] = make_float2(acc[1][2] + bb3.x, acc[1][3] + bb3.y);
        }
    }
}

extern "C" void kernel_launch(void* const* d_in, const int* in_sizes, int n_in,
                              void* d_out, int out_size)
{
    const float* x   = (const float*)d_in[0];
    const float* W1  = (const float*)d_in[1];
    const float* b1  = (const float*)d_in[2];
    const float* W2  = (const float*)d_in[3];
    const float* b2  = (const float*)d_in[4];
    const float* W3  = (const float*)d_in[5];
    const float* b3  = (const float*)d_in[6];
    const float* Wg1 = (const float*)d_in[7];
    const float* bg1 = (const float*)d_in[8];
    const float* Wg2 = (const float*)d_in[9];
    const float* bg2 = (const float*)d_in[10];
    float* out = (float*)d_out;

    const int B  = in_sizes[0] / DI;
    const int NT = (B + 127) / 128;

    int nsm = 148;
    cudaDeviceGetAttribute(&nsm, cudaDevAttrMultiProcessorCount, 0);
    int grid = 2 * nsm;
    if (grid > NT) grid = NT;

    moe_mma_kernel<<<grid, 128>>>(x, W1, b1, W2, b2, W3, b3,
                                  Wg1, bg1, Wg2, bg2, out, B, NT);
}

// round 14
// speedup vs baseline: 3.7743x; 1.0586x over previous
#include <cuda_runtime.h>
#include <cuda_fp16.h>
#include <cstdint>

// MoE dense 8-expert: D_IN=6, H=32, D_OUT=2, B=1M, fp32.
// R14 = R13 (all four GEMMs incl. gate+layer-3 on fp16 mma.sync, MMA count at
// the fragment-shape minimum) with occupancy 2 -> 3 CTAs/SM. regs=136 fits
// the 170-reg/3-CTA budget; third warp per SMSP covers the measured 58%
// issue-stall (cvt chains + HMMA latency).

#define ED 8
#define DI 6
#define HH 32
#define DO 2

typedef unsigned long long u64;
typedef unsigned int u32;

// pack two f32 -> f16x2 (element0 = lo_e arg, element1 = hi_e arg)
__device__ __forceinline__ u32 f16x2_of(float lo_e, float hi_e) {
    u32 r; asm("cvt.rn.f16x2.f32 %0, %1, %2;" : "=r"(r) : "f"(hi_e), "f"(lo_e)); return r;
}
__device__ __forceinline__ u32 hmax2z(u32 a) {
    u32 r; asm("max.f16x2 %0, %1, %2;" : "=r"(r) : "r"(a), "r"(0u)); return r;
}
__device__ __forceinline__ u32 hmul2(u32 a, u32 b) {
    u32 r; asm("mul.f16x2 %0, %1, %2;" : "=r"(r) : "r"(a), "r"(b)); return r;
}
__device__ __forceinline__ void ffma2_acc(u64& acc, u64 a, u64 b) {
    asm("fma.rn.f32x2 %0, %1, %2, %0;" : "+l"(acc) : "l"(a), "l"(b));
}
__device__ __forceinline__ u64 mul2(u64 a, u64 b) {
    u64 r; asm("mul.rn.f32x2 %0, %1, %2;" : "=l"(r) : "l"(a), "l"(b)); return r;
}
__device__ __forceinline__ u64 add2(u64 a, u64 b) {
    u64 r; asm("add.rn.f32x2 %0, %1, %2;" : "=l"(r) : "l"(a), "l"(b)); return r;
}
__device__ __forceinline__ u64 pack_dup(float v) {
    u64 r; asm("mov.b64 %0, {%1, %1};" : "=l"(r) : "r"(__float_as_uint(v))); return r;
}
__device__ __forceinline__ float2 unpack2(u64 v) {
    float2 f; asm("mov.b64 {%0, %1}, %2;" : "=f"(f.x), "=f"(f.y) : "l"(v)); return f;
}

// ---- MMA helpers (fp16 in, fp32 accum) ----
__device__ __forceinline__ void mma_f16(float& d0, float& d1, float& d2, float& d3,
                                        u32 a0, u32 a1, u32 a2, u32 a3,
                                        u32 b0, u32 b1) {
    asm("mma.sync.aligned.m16n8k16.row.col.f32.f16.f16.f32 "
        "{%0,%1,%2,%3}, {%4,%5,%6,%7}, {%8,%9}, {%0,%1,%2,%3};"
        : "+f"(d0), "+f"(d1), "+f"(d2), "+f"(d3)
        : "r"(a0), "r"(a1), "r"(a2), "r"(a3), "r"(b0), "r"(b1));
}
__device__ __forceinline__ void mma_f16_c(float& d0, float& d1, float& d2, float& d3,
                                          u32 a0, u32 a1, u32 a2, u32 a3,
                                          u32 b0, u32 b1,
                                          float c0, float c1, float c2, float c3) {
    asm("mma.sync.aligned.m16n8k16.row.col.f32.f16.f16.f32 "
        "{%0,%1,%2,%3}, {%4,%5,%6,%7}, {%8,%9}, {%10,%11,%12,%13};"
        : "=f"(d0), "=f"(d1), "=f"(d2), "=f"(d3)
        : "r"(a0), "r"(a1), "r"(a2), "r"(a3), "r"(b0), "r"(b1),
          "f"(c0), "f"(c1), "f"(c2), "f"(c3));
}
__device__ __forceinline__ void mma_f16_k8_c(float& d0, float& d1, float& d2, float& d3,
                                             u32 a0, u32 a1, u32 b0,
                                             float c0, float c1, float c2, float c3) {
    asm("mma.sync.aligned.m16n8k8.row.col.f32.f16.f16.f32 "
        "{%0,%1,%2,%3}, {%4,%5}, {%6}, {%7,%8,%9,%10};"
        : "=f"(d0), "=f"(d1), "=f"(d2), "=f"(d3)
        : "r"(a0), "r"(a1), "r"(b0),
          "f"(c0), "f"(c1), "f"(c2), "f"(c3));
}

__global__ __launch_bounds__(128, 3)
void moe_mma_kernel(const float* __restrict__ gx,
                    const float* __restrict__ gW1, const float* __restrict__ gb1,
                    const float* __restrict__ gW2, const float* __restrict__ gb2,
                    const float* __restrict__ gW3, const float* __restrict__ gb3,
                    const float* __restrict__ gWg1, const float* __restrict__ gbg1,
                    const float* __restrict__ gWg2, const float* __restrict__ gbg2,
                    float* __restrict__ gout, int B, int NT)
{
    __shared__ __align__(16) float sx[4 * 192];               // per-warp x tiles
    __shared__ __align__(16) char  sBfrag[ED * 4 * 32 * 16];  // layer-2 W2 fp16 frags
    __shared__ __align__(16) char  sB1frag[ED * 32 * 16];     // layer-1 W1 fp16 frags, b1 @k=6
    __shared__ __align__(16) char  sG1frag[32 * 16];          // gate Wg1 frag, bg1 @k=6
    __shared__ __align__(16) char  sG2frag[32 * 16];          // gate Wg2 frag (K=32, N=8)
    __shared__ __align__(16) float sb2[ED * HH];

    const int tid  = threadIdx.x;
    const int w    = tid >> 5;
    const int lane = tid & 31;
    const int g    = lane >> 2;   // groupID
    const int q    = lane & 3;    // threadID in group

    // ---- stage small weights ----
    for (int i = tid; i < ED * HH; i += 128) sb2[i] = gb2[i];

    // ---- precompute per-lane B fragments (fp16) ----
    for (int e = w * 2; e < w * 2 + 2; e++) {
        // layer-2: chunk c = kf*2 + nf_half
        #pragma unroll
        for (int c = 0; c < 4; c++) {
            const int kf = c >> 1, nfh = c & 1;
            u32 hi4[4];
            #pragma unroll
            for (int p = 0; p < 2; p++) {
                const int n  = (nfh * 2 + p) * 8 + g;
                const int k0 = kf * 16 + 2 * q;
                hi4[p * 2 + 0] = f16x2_of(gW2[e * 1024 + (k0    ) * 32 + n],
                                          gW2[e * 1024 + (k0 + 1) * 32 + n]);
                hi4[p * 2 + 1] = f16x2_of(gW2[e * 1024 + (k0 + 8) * 32 + n],
                                          gW2[e * 1024 + (k0 + 9) * 32 + n]);
            }
            *(uint4*)(sBfrag + ((e * 4 + c) * 32 + lane) * 16) = make_uint4(hi4[0], hi4[1], hi4[2], hi4[3]);
        }
        // layer-1 (k8 frag; q==3 carries b1 at k=6, 0 at k=7)
        {
            u32 hi4[4];
            #pragma unroll
            for (int nf = 0; nf < 4; nf++) {
                const int n = nf * 8 + g;
                float w0, w1;
                if (q < 3) {
                    w0 = gW1[e * 192 + (2 * q    ) * 32 + n];
                    w1 = gW1[e * 192 + (2 * q + 1) * 32 + n];
                } else {
                    w0 = gb1[e * 32 + n];
                    w1 = 0.0f;
                }
                hi4[nf] = f16x2_of(w0, w1);
            }
            *(uint4*)(sB1frag + (e * 32 + lane) * 16) = make_uint4(hi4[0], hi4[1], hi4[2], hi4[3]);
        }
    }
    // gate layer-1 frag (bg1 @k=6)
    if (w == 0) {
        u32 hi4[4];
        #pragma unroll
        for (int nf = 0; nf < 4; nf++) {
            const int n = nf * 8 + g;
            float w0, w1;
            if (q < 3) {
                w0 = gWg1[(2 * q    ) * 32 + n];
                w1 = gWg1[(2 * q + 1) * 32 + n];
            } else {
                w0 = gbg1[n];
                w1 = 0.0f;
            }
            hi4[nf] = f16x2_of(w0, w1);
        }
        *(uint4*)(sG1frag + lane * 16) = make_uint4(hi4[0], hi4[1], hi4[2], hi4[3]);
    }
    // gate layer-2 frag: K=32, N=8 (n=g); Wg2 is [HH, ED]
    if (w == 1) {
        u32 f4[4];
        #pragma unroll
        for (int kf = 0; kf < 2; kf++) {
            const int k0 = kf * 16 + 2 * q;
            f4[kf * 2 + 0] = f16x2_of(gWg2[(k0    ) * ED + g], gWg2[(k0 + 1) * ED + g]);
            f4[kf * 2 + 1] = f16x2_of(gWg2[(k0 + 8) * ED + g], gWg2[(k0 + 9) * ED + g]);
        }
        *(uint4*)(sG2frag + lane * 16) = make_uint4(f4[0], f4[1], f4[2], f4[3]);
    }
    __syncthreads();

    // ---- layer-3 W3 B-fragments, hoisted into registers (K=32, N=8; cols>=2 zero) ----
    u32 w3f[ED][4];
    #pragma unroll
    for (int e = 0; e < ED; e++) {
        #pragma unroll
        for (int kf = 0; kf < 2; kf++) {
            const int k0 = kf * 16 + 2 * q;
            u32 b0 = 0, b1 = 0;
            if (g < 2) {
                b0 = f16x2_of(gW3[e * 64 + (k0    ) * DO + g], gW3[e * 64 + (k0 + 1) * DO + g]);
                b1 = f16x2_of(gW3[e * 64 + (k0 + 8) * DO + g], gW3[e * 64 + (k0 + 9) * DO + g]);
            }
            w3f[e][kf * 2 + 0] = b0;
            w3f[e][kf * 2 + 1] = b1;
        }
    }
    // b3 pairs for this lane's two experts (2q, 2q+1), packed f32x2
    const u64 b3q0 = *(const u64*)&gb3[(2 * q    ) * DO];
    const u64 b3q1 = *(const u64*)&gb3[(2 * q + 1) * DO];

    const int lim6 = B * DI;
    const float fz = 0.0f;
    const float2 bg2c = ((const float2*)gbg2)[q];   // gate C-operand cols 2q, 2q+1

    // ---- persistent per-warp tile loop (32 tokens per warp) ----
    for (int tile = blockIdx.x; tile < NT; tile += gridDim.x) {
        const int base = tile * 128 + w * 32;
        float* sxw = sx + w * 192;
        #pragma unroll
        for (int i = 0; i < 6; i++) {
            const int idx = base * DI + i * 32 + lane;
            sxw[i * 32 + lane] = (idx < lim6) ? gx[idx] : 0.0f;
        }
        __syncwarp();

        // ---- x A-fragments (fp16, k8 layout); q==3 -> 1.0 bias slot ----
        u32 xhi[2][2];
        #pragma unroll
        for (int mf = 0; mf < 2; mf++) {
            const int r0 = 16 * mf + g, r1 = r0 + 8;
            float v00, v01, v10, v11;
            if (q < 3) {
                v00 = sxw[r0 * DI + 2 * q]; v01 = sxw[r0 * DI + 2 * q + 1];
                v10 = sxw[r1 * DI + 2 * q]; v11 = sxw[r1 * DI + 2 * q + 1];
            } else {
                v00 = 1.0f; v01 = 0.0f; v10 = 1.0f; v11 = 0.0f;
            }
            xhi[mf][0] = f16x2_of(v00, v01);
            xhi[mf][1] = f16x2_of(v10, v11);
        }

        // ---- GATE via MMA + quad-butterfly softmax ----
        float glane[4][2];   // [m][j]: gate for (row g+8m, expert 2q+j)
        {
            const uint4 g1f = *(const uint4*)(sG1frag + lane * 16);
            float hgd[2][4][4];
            #pragma unroll
            for (int nf = 0; nf < 4; nf++) {
                const u32 bh = (nf == 0) ? g1f.x : (nf == 1) ? g1f.y : (nf == 2) ? g1f.z : g1f.w;
                #pragma unroll
                for (int mf = 0; mf < 2; mf++) {
                    mma_f16_k8_c(hgd[mf][nf][0], hgd[mf][nf][1], hgd[mf][nf][2], hgd[mf][nf][3],
                                 xhi[mf][0], xhi[mf][1], bh, fz, fz, fz, fz);
                }
            }
            u32 ag[2][2][4];
            #pragma unroll
            for (int mf = 0; mf < 2; mf++) {
                #pragma unroll
                for (int nf = 0; nf < 4; nf++) {
                    const int kf = nf >> 1, half = nf & 1;
                    ag[mf][kf][half * 2 + 0] = hmax2z(f16x2_of(hgd[mf][nf][0], hgd[mf][nf][1]));
                    ag[mf][kf][half * 2 + 1] = hmax2z(f16x2_of(hgd[mf][nf][2], hgd[mf][nf][3]));
                }
            }
            const uint4 g2f = *(const uint4*)(sG2frag + lane * 16);
            float gl[2][4];
            #pragma unroll
            for (int mf = 0; mf < 2; mf++) {
                mma_f16_c(gl[mf][0], gl[mf][1], gl[mf][2], gl[mf][3],
                          ag[mf][0][0], ag[mf][0][1], ag[mf][0][2], ag[mf][0][3],
                          g2f.x, g2f.y,
                          bg2c.x, bg2c.y, bg2c.x, bg2c.y);
                mma_f16(gl[mf][0], gl[mf][1], gl[mf][2], gl[mf][3],
                        ag[mf][1][0], ag[mf][1][1], ag[mf][1][2], ag[mf][1][3],
                        g2f.z, g2f.w);
            }
            #pragma unroll
            for (int mf = 0; mf < 2; mf++) {
                #pragma unroll
                for (int r = 0; r < 2; r++) {
                    const int m = 2 * mf + r;
                    const float l0 = gl[mf][r * 2 + 0];
                    const float l1 = gl[mf][r * 2 + 1];
                    float mx = fmaxf(l0, l1);
                    mx = fmaxf(mx, __shfl_xor_sync(0xffffffffu, mx, 1));
                    mx = fmaxf(mx, __shfl_xor_sync(0xffffffffu, mx, 2));
                    const float e0 = __expf(l0 - mx);
                    const float e1 = __expf(l1 - mx);
                    float s = e0 + e1;
                    s += __shfl_xor_sync(0xffffffffu, s, 1);
                    s += __shfl_xor_sync(0xffffffffu, s, 2);
                    const float inv = 1.0f / s;
                    glane[m][0] = e0 * inv;
                    glane[m][1] = e1 * inv;
                }
            }
        }

        // persistent layer-3 accumulator (D over all experts); init via C on e==0
        float acc[2][4];

        // ---- experts ----
        #pragma unroll
        for (int e = 0; e < ED; e++) {
            const uint4 b1f = *(const uint4*)(sB1frag + (e * 32 + lane) * 16);
            uint4 cH[4];
            #pragma unroll
            for (int c = 0; c < 4; c++)
                cH[c] = *(const uint4*)(sBfrag + ((e * 4 + c) * 32 + lane) * 16);

            // layer 1: ONE k8 MMA per (nf,mf)
            float h1d[2][4][4];
            #pragma unroll
            for (int nf = 0; nf < 4; nf++) {
                const u32 bh = (nf == 0) ? b1f.x : (nf == 1) ? b1f.y : (nf == 2) ? b1f.z : b1f.w;
                #pragma unroll
                for (int mf = 0; mf < 2; mf++) {
                    mma_f16_k8_c(h1d[mf][nf][0], h1d[mf][nf][1], h1d[mf][nf][2], h1d[mf][nf][3],
                                 xhi[mf][0], xhi[mf][1], bh, fz, fz, fz, fz);
                }
            }

            // relu in fp16 + pack -> layer-2 A frags
            u32 ahi[2][2][4];
            #pragma unroll
            for (int mf = 0; mf < 2; mf++) {
                #pragma unroll
                for (int nf = 0; nf < 4; nf++) {
                    const int kf = nf >> 1, half = nf & 1;
                    ahi[mf][kf][half * 2 + 0] = hmax2z(f16x2_of(h1d[mf][nf][0], h1d[mf][nf][1]));
                    ahi[mf][kf][half * 2 + 1] = hmax2z(f16x2_of(h1d[mf][nf][2], h1d[mf][nf][3]));
                }
            }

            // b2 bias fragments
            float2 b2p[4];
            #pragma unroll
            for (int nf = 0; nf < 4; nf++)
                b2p[nf] = *(const float2*)&sb2[e * HH + nf * 8 + 2 * q];

            // layer-2: TWO k16 MMAs per (nf,mf); b2 via C on the first
            float dd[2][4][4];
            #pragma unroll
            for (int nf = 0; nf < 4; nf++) {
                const uint4 h40 = cH[0 * 2 + (nf >> 1)];
                const uint4 h41 = cH[1 * 2 + (nf >> 1)];
                const u32 b0k0 = (nf & 1) ? h40.z : h40.x;
                const u32 b1k0 = (nf & 1) ? h40.w : h40.y;
                const u32 b0k1 = (nf & 1) ? h41.z : h41.x;
                const u32 b1k1 = (nf & 1) ? h41.w : h41.y;
                #pragma unroll
                for (int mf = 0; mf < 2; mf++) {
                    mma_f16_c(dd[mf][nf][0], dd[mf][nf][1], dd[mf][nf][2], dd[mf][nf][3],
                              ahi[mf][0][0], ahi[mf][0][1], ahi[mf][0][2], ahi[mf][0][3],
                              b0k0, b1k0,
                              b2p[nf].x, b2p[nf].y, b2p[nf].x, b2p[nf].y);
                    mma_f16(dd[mf][nf][0], dd[mf][nf][1], dd[mf][nf][2], dd[mf][nf][3],
                            ahi[mf][1][0], ahi[mf][1][1], ahi[mf][1][2], ahi[mf][1][3],
                            b0k1, b1k1);
                }
            }

            // gate per row as dup'd half2 (g_e > 0, so relu(h2)*g folds into A)
            u32 geh[4];
            #pragma unroll
            for (int m = 0; m < 4; m++) {
                const float ge = __shfl_sync(0xffffffffu, glane[m][e & 1], (lane & 28) + (e >> 1));
                geh[m] = f16x2_of(ge, ge);
            }

            // layer-3 A frags: relu(dd) in fp16 scaled by gate
            u32 a3[2][2][4];
            #pragma unroll
            for (int mf = 0; mf < 2; mf++) {
                #pragma unroll
                for (int nf = 0; nf < 4; nf++) {
                    const int kf = nf >> 1, half = nf & 1;
                    a3[mf][kf][half * 2 + 0] =
                        hmul2(hmax2z(f16x2_of(dd[mf][nf][0], dd[mf][nf][1])), geh[2 * mf + 0]);
                    a3[mf][kf][half * 2 + 1] =
                        hmul2(hmax2z(f16x2_of(dd[mf][nf][2], dd[mf][nf][3])), geh[2 * mf + 1]);
                }
            }

            // layer-3 MMAs, accumulating across experts (C=0 on very first)
            #pragma unroll
            for (int mf = 0; mf < 2; mf++) {
                if (e == 0) {
                    mma_f16_c(acc[mf][0], acc[mf][1], acc[mf][2], acc[mf][3],
                              a3[mf][0][0], a3[mf][0][1], a3[mf][0][2], a3[mf][0][3],
                              w3f[e][0], w3f[e][1], fz, fz, fz, fz);
                } else {
                    mma_f16(acc[mf][0], acc[mf][1], acc[mf][2], acc[mf][3],
                            a3[mf][0][0], a3[mf][0][1], a3[mf][0][2], a3[mf][0][3],
                            w3f[e][0], w3f[e][1]);
                }
                mma_f16(acc[mf][0], acc[mf][1], acc[mf][2], acc[mf][3],
                        a3[mf][1][0], a3[mf][1][1], a3[mf][1][2], a3[mf][1][3],
                        w3f[e][2], w3f[e][3]);
            }
        }

        // ---- b3 tail: bias[m] = sum_e g[row][e]*b3[e][:], via quad butterflies ----
        u64 bias[4];
        #pragma unroll
        for (int m = 0; m < 4; m++) {
            u64 p = mul2(pack_dup(glane[m][0]), b3q0);
            ffma2_acc(p, pack_dup(glane[m][1]), b3q1);
            p = add2(p, __shfl_xor_sync(0xffffffffu, p, 1));
            p = add2(p, __shfl_xor_sync(0xffffffffu, p, 2));
            bias[m] = p;
        }

        // ---- store: q==0 lanes hold cols 0,1 for rows g+8m ----
        if (q == 0) {
            const float2 bb0 = unpack2(bias[0]);
            const float2 bb1 = unpack2(bias[1]);
            const float2 bb2 = unpack2(bias[2]);
            const float2 bb3 = unpack2(bias[3]);
            const int t0 = base + g;
            if (t0 < B)      ((float2*)gout)[t0]      = make_float2(acc[0][0] + bb0.x, acc[0][1] + bb0.y);
            if (t0 + 8 < B)  ((float2*)gout)[t0 + 8]  = make_float2(acc[0][2] + bb1.x, acc[0][3] + bb1.y);
            if (t0 + 16 < B) ((float2*)gout)[t0 + 16] = make_float2(acc[1][0] + bb2.x, acc[1][1] + bb2.y);
            if (t0 + 24 < B) ((float2*)gout)[t0 + 24] = make_float2(acc[1][2] + bb3.x, acc[1][3] + bb3.y);
        }
    }
}

extern "C" void kernel_launch(void* const* d_in, const int* in_sizes, int n_in,
                              void* d_out, int out_size)
{
    const float* x   = (const float*)d_in[0];
    const float* W1  = (const float*)d_in[1];
    const float* b1  = (const float*)d_in[2];
    const float* W2  = (const float*)d_in[3];
    const float* b2  = (const float*)d_in[4];
    const float* W3  = (const float*)d_in[5];
    const float* b3  = (const float*)d_in[6];
    const float* Wg1 = (const float*)d_in[7];
    const float* bg1 = (const float*)d_in[8];
    const float* Wg2 = (const float*)d_in[9];
    const float* bg2 = (const float*)d_in[10];
    float* out = (float*)d_out;

    const int B  = in_sizes[0] / DI;
    const int NT = (B + 127) / 128;

    int nsm = 148;
    cudaDeviceGetAttribute(&nsm, cudaDevAttrMultiProcessorCount, 0);
    int grid = 3 * nsm;          // 3 CTAs/SM
    if (grid > NT) grid = NT;

    moe_mma_kernel<<<grid, 128>>>(x, W1, b1, W2, b2, W3, b3,
                                  Wg1, bg1, Wg2, bg2, out, B, NT);
}